// round 9
// baseline (speedup 1.0000x reference)
#include <cuda_runtime.h>
#include <cuda_bf16.h>
#include <cstdint>
#include <math.h>

// Problem constants
#define BB   128
#define LLEN 52
#define TT   51
#define EE   512
#define DD   512
#define VV   10000
#define FEATN 2048
#define NPP  196
#define G4   2048
#define KK   512
#define MROWS (BB*TT)        // 6528

// ---------------- scratch ----------------
__device__ float g_X[(size_t)MROWS * G4];
__device__ float g_H[(size_t)MROWS * DD];
__device__ float g_feats[(size_t)BB * FEATN];
__device__ float g_hbuf[2][BB * DD];
__device__ float g_c[BB * DD];
__device__ int   g_sort[BB];
__device__ int   g_declen[BB];
__device__ int   g_capsS[BB * LLEN];
__device__ int   g_rowmap[MROWS];
__device__ unsigned g_bar;
// bf16 split buffers (A reused for emb-gather then H; B reused for w_ih then word_w)
__device__ __nv_bfloat16 g_Ahi[(size_t)MROWS * KK];
__device__ __nv_bfloat16 g_Alo[(size_t)MROWS * KK];
__device__ __nv_bfloat16 g_Bhi[(size_t)VV * KK];
__device__ __nv_bfloat16 g_Blo[(size_t)VV * KK];

// ---------------- small helpers ----------------
__device__ __forceinline__ uint32_t smem_u32(const void* p) {
    return (uint32_t)__cvta_generic_to_shared(p);
}
__device__ __forceinline__ void ldsm_x4(uint32_t* r, uint32_t addr) {
    asm volatile("ldmatrix.sync.aligned.m8n8.x4.shared.b16 {%0,%1,%2,%3}, [%4];"
                 : "=r"(r[0]), "=r"(r[1]), "=r"(r[2]), "=r"(r[3]) : "r"(addr));
}
__device__ __forceinline__ void mma_bf16(float* c, const uint32_t* a, const uint32_t* b) {
    asm volatile("mma.sync.aligned.m16n8k16.row.col.f32.bf16.bf16.f32 "
                 "{%0,%1,%2,%3},{%4,%5,%6,%7},{%8,%9},{%0,%1,%2,%3};"
                 : "+f"(c[0]), "+f"(c[1]), "+f"(c[2]), "+f"(c[3])
                 : "r"(a[0]), "r"(a[1]), "r"(a[2]), "r"(a[3]), "r"(b[0]), "r"(b[1]));
}
__device__ __forceinline__ void cp_async16(uint32_t dst, const void* src, int src_bytes) {
    asm volatile("cp.async.cg.shared.global [%0], [%1], 16, %2;"
                 :: "r"(dst), "l"(src), "r"(src_bytes) : "memory");
}

// ---------------- sort / gather ----------------
__global__ void k_sort(const int* __restrict__ caplen, const int* __restrict__ caps,
                       float* __restrict__ out, long long out_size) {
    __shared__ int lens[BB];
    int b = threadIdx.x;
    lens[b] = caplen[b];
    if (b == 0) g_bar = 0u;
    __syncthreads();
    int my = lens[b];
    int rank = 0;
    for (int j = 0; j < BB; j++) {
        int lj = lens[j];
        if (lj > my || (lj == my && j < b)) rank++;
    }
    g_sort[rank] = b;
    __syncthreads();
    int s = g_sort[b];
    int dl = lens[s] - 1;
    g_declen[b] = dl;
    for (int l = 0; l < LLEN; l++) g_capsS[b * LLEN + l] = caps[s * LLEN + l];
    for (int t = 0; t < TT; t++)   g_rowmap[b * TT + t] = g_capsS[b * LLEN + t];
    for (int d = 0; d < DD; d++)   g_c[b * DD + d] = 0.0f;
    long long off = (long long)MROWS * VV;
    if (out_size >= off + (long long)BB * LLEN + 2 * BB) {
        for (int l = 0; l < LLEN; l++) out[off + b * LLEN + l] = (float)g_capsS[b * LLEN + l];
        out[off + (long long)BB * LLEN + b]      = (float)dl;
        out[off + (long long)BB * LLEN + BB + b] = (float)s;
    }
}

// ---------------- mean features ----------------
__global__ __launch_bounds__(256) void k_mean(const float* __restrict__ img) {
    int p = blockIdx.x;
    int s = g_sort[p];
    const float* base = img + (long long)s * NPP * FEATN;
    int f0 = threadIdx.x;
    float acc[8] = {0,0,0,0,0,0,0,0};
    for (int q = 0; q < NPP; q++) {
        const float* rowp = base + (long long)q * FEATN;
        #pragma unroll
        for (int u = 0; u < 8; u++) acc[u] += rowp[f0 + u * 256];
    }
    #pragma unroll
    for (int u = 0; u < 8; u++)
        g_feats[(long long)p * FEATN + f0 + u * 256] = acc[u] * (1.0f / 196.0f);
}

// ---------------- SIMT GEMM (small h0 only) ----------------
template<int BM, int BN, int BK, int TM, int TN>
__global__ __launch_bounds__((BM/TM)*(BN/TN)) void gemm_nt(
    const float* __restrict__ A, int lda,
    const float* __restrict__ B, int ldb,
    const float* __restrict__ bias1,
    float* __restrict__ C, int ldc, int K)
{
    constexpr int NT = (BM / TM) * (BN / TN);
    __shared__ float As[BK][BM + 4];
    __shared__ float Bs[BK][BN + 4];
    const int tid = threadIdx.x;
    const int tx = tid % (BN / TN);
    const int ty = tid / (BN / TN);
    const int row0 = blockIdx.y * BM;
    const int col0 = blockIdx.x * BN;

    float acc[TM][TN];
    #pragma unroll
    for (int i = 0; i < TM; i++)
        #pragma unroll
        for (int j = 0; j < TN; j++) acc[i][j] = 0.0f;

    for (int k0 = 0; k0 < K; k0 += BK) {
        for (int e = tid; e < BM * BK; e += NT) {
            int r = e / BK, k = e % BK;
            As[k][r] = A[(long long)(row0 + r) * lda + k0 + k];
        }
        for (int e = tid; e < BN * BK; e += NT) {
            int c = e / BK, k = e % BK;
            Bs[k][c] = B[(long long)(col0 + c) * ldb + k0 + k];
        }
        __syncthreads();
        #pragma unroll
        for (int kk = 0; kk < BK; kk++) {
            float ra[TM], rb[TN];
            #pragma unroll
            for (int i = 0; i < TM; i += 4) {
                float4 v = *reinterpret_cast<const float4*>(&As[kk][ty * TM + i]);
                ra[i] = v.x; ra[i+1] = v.y; ra[i+2] = v.z; ra[i+3] = v.w;
            }
            #pragma unroll
            for (int j = 0; j < TN; j += 4) {
                float4 v = *reinterpret_cast<const float4*>(&Bs[kk][tx * TN + j]);
                rb[j] = v.x; rb[j+1] = v.y; rb[j+2] = v.z; rb[j+3] = v.w;
            }
            #pragma unroll
            for (int i = 0; i < TM; i++)
                #pragma unroll
                for (int j = 0; j < TN; j++)
                    acc[i][j] += ra[i] * rb[j];
        }
        __syncthreads();
    }
    #pragma unroll
    for (int i = 0; i < TM; i++) {
        int gr = row0 + ty * TM + i;
        #pragma unroll
        for (int j = 0; j < TN; j++) {
            int gc = col0 + tx * TN + j;
            C[(long long)gr * ldc + gc] = acc[i][j] + bias1[gc];
        }
    }
}

// ---------------- bf16 split helpers ----------------
__device__ __forceinline__ void split2(float a, float b, uint32_t& h, uint32_t& l) {
    __nv_bfloat16 ha = __float2bfloat16(a);
    __nv_bfloat16 hb = __float2bfloat16(b);
    float ra = a - __bfloat162float(ha);
    float rb = b - __bfloat162float(hb);
    __nv_bfloat16 la = __float2bfloat16(ra);
    __nv_bfloat16 lb = __float2bfloat16(rb);
    h = ((uint32_t)__bfloat16_as_ushort(hb) << 16) | (uint32_t)__bfloat16_as_ushort(ha);
    l = ((uint32_t)__bfloat16_as_ushort(lb) << 16) | (uint32_t)__bfloat16_as_ushort(la);
}

__global__ __launch_bounds__(256) void k_split(const float4* __restrict__ src,
                                               uint2* __restrict__ hi, uint2* __restrict__ lo, int n4) {
    int i = blockIdx.x * 256 + threadIdx.x;
    if (i >= n4) return;
    float4 v = src[i];
    uint2 h, l;
    split2(v.x, v.y, h.x, l.x);
    split2(v.z, v.w, h.y, l.y);
    hi[i] = h;
    lo[i] = l;
}

__global__ __launch_bounds__(128) void k_split_emb(const float* __restrict__ emb) {
    int m = blockIdx.x;
    int tok = g_rowmap[m];
    float4 v = reinterpret_cast<const float4*>(emb + (long long)tok * EE)[threadIdx.x];
    uint2 h, l;
    split2(v.x, v.y, h.x, l.x);
    split2(v.z, v.w, h.y, l.y);
    reinterpret_cast<uint2*>(g_Ahi + (long long)m * KK)[threadIdx.x] = h;
    reinterpret_cast<uint2*>(g_Alo + (long long)m * KK)[threadIdx.x] = l;
}

// ---------------- mma.sync bf16 3-pass split GEMM (cp.async double-buffered) ----------------
// C[M x Ncols] = A @ B^T (+bias), A: M x 512 hi/lo, B: Ncols x 512 hi/lo
// CTA 128x128, BK=32, 8 warps (4m x 2n), warp tile 32x64.
// MODE 0: C = acc + bias1 (+ bias2) ; MODE 2: C = mask(row)*(acc + bias1)
#define MG_TILE_ELEMS (128 * 40)                       // per-operand smem tile (stride 40)
#define MG_STAGE_BYTES (4 * MG_TILE_ELEMS * 2)         // 40960
#define MG_SMEM (2 * MG_STAGE_BYTES)                   // 81920

template<int MODE>
__global__ __launch_bounds__(256)
void mma_gemm(const __nv_bfloat16* __restrict__ Ahi, const __nv_bfloat16* __restrict__ Alo,
              const __nv_bfloat16* __restrict__ Bhi, const __nv_bfloat16* __restrict__ Blo,
              const float* __restrict__ bias1, const float* __restrict__ bias2,
              float* __restrict__ C, int ldc, int Ncols,
              const int* __restrict__ declen)
{
    extern __shared__ __align__(16) __nv_bfloat16 smp[];   // [2][4][128*40]
    const int tid  = threadIdx.x;
    const int lane = tid & 31;
    const int w    = tid >> 5;
    const int wm   = w >> 1;       // 0..3
    const int wn   = w & 1;        // 0..1
    const int row0 = blockIdx.y * 128;
    const int col0 = blockIdx.x * 128;
    const int mat  = lane >> 3;    // ldmatrix matrix id
    const int mr   = lane & 7;

    float acc[2][8][4];
    #pragma unroll
    for (int i = 0; i < 2; i++)
        #pragma unroll
        for (int j = 0; j < 8; j++)
            #pragma unroll
            for (int q = 0; q < 4; q++) acc[i][j][q] = 0.0f;

    // stage chunk ch's 4 operand tiles into buffer buf via cp.async (one commit group)
    auto stage_load = [&](int ch, int buf) {
        const int k0 = ch * 32;
        __nv_bfloat16* base = smp + (size_t)buf * 4 * MG_TILE_ELEMS;
        #pragma unroll
        for (int e = tid; e < 2048; e += 256) {
            int tsel = e >> 9;         // 0 Ahi, 1 Alo, 2 Bhi, 3 Blo
            int i = e & 511;
            int r = i >> 2, q = i & 3;
            const __nv_bfloat16* src;
            int sz = 16;
            if (tsel < 2) {
                src = (tsel == 0 ? Ahi : Alo) + (size_t)(row0 + r) * KK + k0 + q * 8;
            } else {
                int gc = col0 + r;
                int gcs = (gc < Ncols) ? gc : 0;
                src = (tsel == 2 ? Bhi : Blo) + (size_t)gcs * KK + k0 + q * 8;
                sz = (gc < Ncols) ? 16 : 0;    // zero-fill rows past N edge
            }
            cp_async16(smem_u32(base + tsel * MG_TILE_ELEMS + r * 40 + q * 8), src, sz);
        }
        asm volatile("cp.async.commit_group;" ::: "memory");
    };

    stage_load(0, 0);

    for (int ch = 0; ch < 16; ch++) {
        if (ch + 1 < 16) {
            stage_load(ch + 1, (ch + 1) & 1);
            asm volatile("cp.async.wait_group 1;" ::: "memory");   // chunk ch's group done
        } else {
            asm volatile("cp.async.wait_group 0;" ::: "memory");
        }
        __syncthreads();

        const uint32_t sbase = smem_u32(smp) + (uint32_t)((ch & 1) * MG_STAGE_BYTES);
        const uint32_t sA0 = sbase;
        const uint32_t sA1 = sbase + MG_TILE_ELEMS * 2;
        const uint32_t sB0 = sbase + MG_TILE_ELEMS * 4;
        const uint32_t sB1 = sbase + MG_TILE_ELEMS * 6;

        #pragma unroll
        for (int kk = 0; kk < 32; kk += 16) {
            uint32_t ahi[2][4], alo[2][4], bhi[8][2], blo[8][2];
            const int acol = kk + ((mat >> 1) << 3);
            const int bcolA = kk + ((mat & 1) << 3);
            // A hi frags
            #pragma unroll
            for (int mi = 0; mi < 2; mi++) {
                int rrow = wm * 32 + mi * 16 + mr + ((mat & 1) << 3);
                ldsm_x4(ahi[mi], sA0 + (uint32_t)(rrow * 40 + acol) * 2);
            }
            // B hi frags
            #pragma unroll
            for (int j2 = 0; j2 < 4; j2++) {
                int nrow = wn * 64 + j2 * 16 + mr + ((mat >> 1) << 3);
                uint32_t r4[4];
                ldsm_x4(r4, sB0 + (uint32_t)(nrow * 40 + bcolA) * 2);
                bhi[2*j2][0] = r4[0]; bhi[2*j2][1] = r4[1];
                bhi[2*j2+1][0] = r4[2]; bhi[2*j2+1][1] = r4[3];
            }
            // pass 1: Ahi * Bhi
            #pragma unroll
            for (int mi = 0; mi < 2; mi++)
                #pragma unroll
                for (int j = 0; j < 8; j++)
                    mma_bf16(acc[mi][j], ahi[mi], bhi[j]);
            // B lo frags, pass 2: Ahi * Blo
            #pragma unroll
            for (int j2 = 0; j2 < 4; j2++) {
                int nrow = wn * 64 + j2 * 16 + mr + ((mat >> 1) << 3);
                uint32_t r4[4];
                ldsm_x4(r4, sB1 + (uint32_t)(nrow * 40 + bcolA) * 2);
                blo[2*j2][0] = r4[0]; blo[2*j2][1] = r4[1];
                blo[2*j2+1][0] = r4[2]; blo[2*j2+1][1] = r4[3];
            }
            #pragma unroll
            for (int mi = 0; mi < 2; mi++)
                #pragma unroll
                for (int j = 0; j < 8; j++)
                    mma_bf16(acc[mi][j], ahi[mi], blo[j]);
            // A lo frags, pass 3: Alo * Bhi
            #pragma unroll
            for (int mi = 0; mi < 2; mi++) {
                int rrow = wm * 32 + mi * 16 + mr + ((mat & 1) << 3);
                ldsm_x4(alo[mi], sA1 + (uint32_t)(rrow * 40 + acol) * 2);
            }
            #pragma unroll
            for (int mi = 0; mi < 2; mi++)
                #pragma unroll
                for (int j = 0; j < 8; j++)
                    mma_bf16(acc[mi][j], alo[mi], bhi[j]);
        }
        __syncthreads();   // protect this buffer before it is re-staged
    }

    // epilogue
    #pragma unroll
    for (int mi = 0; mi < 2; mi++) {
        int gr0 = row0 + wm * 32 + mi * 16 + (lane >> 2);
        float m0 = 1.0f, m1 = 1.0f;
        if (MODE == 2) {
            int b0 = gr0 / TT,       t0 = gr0 - b0 * TT;
            int b1 = (gr0 + 8) / TT, t1 = (gr0 + 8) - b1 * TT;
            m0 = (t0 < declen[b0]) ? 1.0f : 0.0f;
            m1 = (t1 < declen[b1]) ? 1.0f : 0.0f;
        }
        #pragma unroll
        for (int j = 0; j < 8; j++) {
            int gc = col0 + wn * 64 + j * 8 + ((lane & 3) << 1);
            if (gc + 1 < Ncols) {
                float bi0 = bias1[gc], bi1 = bias1[gc + 1];
                if (MODE == 0 && bias2) { bi0 += bias2[gc]; bi1 += bias2[gc + 1]; }
                float2 v0 = make_float2((acc[mi][j][0] + bi0) * m0, (acc[mi][j][1] + bi1) * m0);
                float2 v1 = make_float2((acc[mi][j][2] + bi0) * m1, (acc[mi][j][3] + bi1) * m1);
                *reinterpret_cast<float2*>(&C[(size_t)gr0 * ldc + gc]) = v0;
                *reinterpret_cast<float2*>(&C[(size_t)(gr0 + 8) * ldc + gc]) = v1;
            } else if (gc < Ncols) {
                float bi0 = bias1[gc];
                if (MODE == 0 && bias2) bi0 += bias2[gc];
                C[(size_t)gr0 * ldc + gc]       = (acc[mi][j][0] + bi0) * m0;
                C[(size_t)(gr0 + 8) * ldc + gc] = (acc[mi][j][2] + bi0) * m1;
            }
        }
    }
}

// ---------------- persistent LSTM recurrence ----------------
// 128 CTAs x 256 threads; CTA cid owns hidden dims [4*cid, 4*cid+4) -> 16 gate rows.
// w_hh slice cached in smem for all 51 steps; steps separated by a global barrier.
#define RSW_STRIDE 514
#define RSH_STRIDE 132
#define RSG_STRIDE 20
#define RSMEM_BYTES ((16*RSW_STRIDE + 64*RSH_STRIDE + 128*RSG_STRIDE) * 4)

__global__ __launch_bounds__(256)
void k_recur(const float* __restrict__ w_hh) {
    extern __shared__ float smr[];
    float* sW = smr;                         // [16][514]
    float* sH = sW + 16 * RSW_STRIDE;        // [64][132]
    float* sG = sH + 64 * RSH_STRIDE;        // [128][20]
    const int tid = threadIdx.x;
    const int cid = blockIdx.x;
    const int g   = tid & 15;
    const int bg  = tid >> 4;                // 0..15
    const int b0  = bg * 8;

    // load this CTA's w_hh slice once
    for (int e = tid; e < 16 * 512; e += 256) {
        int gg = e >> 9, k = e & 511;
        int row = ((gg >> 2) << 9) + cid * 4 + (gg & 3);
        sW[gg * RSW_STRIDE + k] = w_hh[(size_t)row * DD + k];
    }

    const int colg = ((g >> 2) << 9) + cid * 4 + (g & 3);

    for (int t = 0; t < TT; t++) {
        const float* hin  = g_hbuf[t & 1];
        float*       hout = g_hbuf[(t + 1) & 1];
        float acc[8] = {0,0,0,0,0,0,0,0};

        for (int kb = 0; kb < DD; kb += 64) {
            __syncthreads();
            for (int e = tid; e < 8192; e += 256) {
                int b = e >> 6, kloc = e & 63;
                sH[kloc * RSH_STRIDE + b] = __ldcg(&hin[b * DD + kb + kloc]);
            }
            __syncthreads();
            const float* wrow = sW + g * RSW_STRIDE + kb;
            #pragma unroll 4
            for (int kloc = 0; kloc < 64; kloc++) {
                float wv = wrow[kloc];
                const float* hr = sH + kloc * RSH_STRIDE + b0;
                float4 h0 = *reinterpret_cast<const float4*>(hr);
                float4 h1 = *reinterpret_cast<const float4*>(hr + 4);
                acc[0] += wv * h0.x; acc[1] += wv * h0.y;
                acc[2] += wv * h0.z; acc[3] += wv * h0.w;
                acc[4] += wv * h1.x; acc[5] += wv * h1.y;
                acc[6] += wv * h1.z; acc[7] += wv * h1.w;
            }
        }
        __syncthreads();
        #pragma unroll
        for (int i = 0; i < 8; i++) {
            int b = b0 + i;
            sG[b * RSG_STRIDE + g] = acc[i] + g_X[(size_t)(b * TT + t) * G4 + colg];
        }
        __syncthreads();
        #pragma unroll
        for (int e = tid; e < 512; e += 256) {
            int b = e >> 2, dl = e & 3;
            float gi = sG[b * RSG_STRIDE + dl];
            float gf = sG[b * RSG_STRIDE + 4 + dl];
            float gg = sG[b * RSG_STRIDE + 8 + dl];
            float go = sG[b * RSG_STRIDE + 12 + dl];
            float si = 1.0f / (1.0f + expf(-gi));
            float sf = 1.0f / (1.0f + expf(-gf));
            float tg = tanhf(gg);
            float so = 1.0f / (1.0f + expf(-go));
            int d = cid * 4 + dl;
            float cold = g_c[b * DD + d];
            float cnew = sf * cold + si * tg;
            float hnew = so * tanhf(cnew);
            g_H[(size_t)(b * TT + t) * DD + d] = hnew;
            bool m = t < g_declen[b];
            hout[b * DD + d] = m ? hnew : __ldcg(&hin[b * DD + d]);
            if (m) g_c[b * DD + d] = cnew;
        }
        // global barrier: release, then acquire-spin
        __threadfence();
        __syncthreads();
        if (tid == 0) {
            atomicAdd(&g_bar, 1u);
            unsigned target = (unsigned)(128 * (t + 1));
            unsigned v;
            do {
                asm volatile("ld.acquire.gpu.u32 %0, [%1];" : "=r"(v) : "l"(&g_bar));
            } while (v < target);
        }
        __syncthreads();
    }
}

// ---------------- launch ----------------
extern "C" void kernel_launch(void* const* d_in, const int* in_sizes, int n_in,
                              void* d_out, int out_size) {
    const float* img    = (const float*)d_in[0];
    const int*   caps   = (const int*)  d_in[1];
    const int*   caplen = (const int*)  d_in[2];
    const float* embtab = (const float*)d_in[3];
    const float* att1_w = (const float*)d_in[4];
    const float* att1_b = (const float*)d_in[5];
    const float* w_ih   = (const float*)d_in[6];
    const float* w_hh   = (const float*)d_in[7];
    const float* b_ih   = (const float*)d_in[8];
    const float* b_hh   = (const float*)d_in[9];
    const float* word_w = (const float*)d_in[10];
    const float* word_b = (const float*)d_in[11];
    float* out = (float*)d_out;

    float *pX, *pH, *pFeats, *pHbuf;
    __nv_bfloat16 *pAhi, *pAlo, *pBhi, *pBlo;
    int *pDeclen;
    cudaGetSymbolAddress((void**)&pX,     g_X);
    cudaGetSymbolAddress((void**)&pH,     g_H);
    cudaGetSymbolAddress((void**)&pFeats, g_feats);
    cudaGetSymbolAddress((void**)&pHbuf,  g_hbuf);
    cudaGetSymbolAddress((void**)&pAhi,   g_Ahi);
    cudaGetSymbolAddress((void**)&pAlo,   g_Alo);
    cudaGetSymbolAddress((void**)&pBhi,   g_Bhi);
    cudaGetSymbolAddress((void**)&pBlo,   g_Blo);
    cudaGetSymbolAddress((void**)&pDeclen,g_declen);

    cudaFuncSetAttribute(k_recur, cudaFuncAttributeMaxDynamicSharedMemorySize, RSMEM_BYTES);
    cudaFuncSetAttribute(mma_gemm<0>, cudaFuncAttributeMaxDynamicSharedMemorySize, MG_SMEM);
    cudaFuncSetAttribute(mma_gemm<2>, cudaFuncAttributeMaxDynamicSharedMemorySize, MG_SMEM);

    // 1) sort / gather / tail outputs / zero c & barrier
    k_sort<<<1, BB>>>(caplen, caps, out, (long long)out_size);
    // 2) mean features (sorted)
    k_mean<<<BB, 256>>>(img);
    // 3) h0 = feats @ att1_w^T + att1_b
    {
        dim3 grid(DD / 64, BB / 64);
        gemm_nt<64, 64, 16, 4, 4><<<grid, 256>>>(
            pFeats, FEATN, att1_w, FEATN, att1_b, pHbuf, DD, FEATN);
    }
    // 4) split w_ih ; gather+split emb
    k_split<<<(G4 * KK / 4 + 255) / 256, 256>>>((const float4*)w_ih, (uint2*)pBhi, (uint2*)pBlo, G4 * KK / 4);
    k_split_emb<<<MROWS, 128>>>(embtab);
    // 5) X = emb @ w_ih^T + b_ih + b_hh  (HMMA, pipelined)
    {
        dim3 grid(G4 / 128, MROWS / 128);
        mma_gemm<0><<<grid, 256, MG_SMEM>>>(pAhi, pAlo, pBhi, pBlo, b_ih, b_hh, pX, G4, G4, nullptr);
    }
    // 6) persistent recurrence (single launch, 51 steps with global barrier)
    k_recur<<<128, 256, RSMEM_BYTES>>>(w_hh);
    // 7) split H and word_w
    k_split<<<(MROWS * DD / 4 + 255) / 256, 256>>>((const float4*)pH, (uint2*)pAhi, (uint2*)pAlo, MROWS * DD / 4);
    k_split<<<(VV * KK / 4 + 255) / 256, 256>>>((const float4*)word_w, (uint2*)pBhi, (uint2*)pBlo, VV * KK / 4);
    // 8) predictions = mask * (H @ word_w^T + word_b)  (HMMA, pipelined)
    {
        dim3 grid((VV + 127) / 128, MROWS / 128);
        mma_gemm<2><<<grid, 256, MG_SMEM>>>(pAhi, pAlo, pBhi, pBlo, word_b, nullptr, out, VV, VV, pDeclen);
    }
}

// round 10
// speedup vs baseline: 1.8405x; 1.8405x over previous
#include <cuda_runtime.h>
#include <cuda_bf16.h>
#include <cstdint>
#include <math.h>

// Problem constants
#define BB   128
#define LLEN 52
#define TT   51
#define EE   512
#define DD   512
#define VV   10000
#define FEATN 2048
#define NPP  196
#define G4   2048
#define KK   512
#define MROWS (BB*TT)        // 6528

// ---------------- scratch ----------------
__device__ float g_X[(size_t)MROWS * G4];
__device__ float g_H[(size_t)MROWS * DD];
__device__ float g_feats[(size_t)BB * FEATN];
__device__ float g_hbuf[2][BB * DD];
__device__ float g_c[BB * DD];
__device__ int   g_sort[BB];
__device__ int   g_declen[BB];
__device__ int   g_capsS[BB * LLEN];
__device__ int   g_rowmap[MROWS];
__device__ unsigned g_bar;
__device__ __nv_bfloat16 g_Ahi[(size_t)MROWS * KK];
__device__ __nv_bfloat16 g_Alo[(size_t)MROWS * KK];
__device__ __nv_bfloat16 g_Bhi[(size_t)VV * KK];
__device__ __nv_bfloat16 g_Blo[(size_t)VV * KK];

// ---------------- small helpers ----------------
__device__ __forceinline__ uint32_t smem_u32(const void* p) {
    return (uint32_t)__cvta_generic_to_shared(p);
}
__device__ __forceinline__ void ldsm_x4(uint32_t* r, uint32_t addr) {
    asm volatile("ldmatrix.sync.aligned.m8n8.x4.shared.b16 {%0,%1,%2,%3}, [%4];"
                 : "=r"(r[0]), "=r"(r[1]), "=r"(r[2]), "=r"(r[3]) : "r"(addr));
}
__device__ __forceinline__ void mma_bf16(float* c, const uint32_t* a, const uint32_t* b) {
    asm volatile("mma.sync.aligned.m16n8k16.row.col.f32.bf16.bf16.f32 "
                 "{%0,%1,%2,%3},{%4,%5,%6,%7},{%8,%9},{%0,%1,%2,%3};"
                 : "+f"(c[0]), "+f"(c[1]), "+f"(c[2]), "+f"(c[3])
                 : "r"(a[0]), "r"(a[1]), "r"(a[2]), "r"(a[3]), "r"(b[0]), "r"(b[1]));
}
__device__ __forceinline__ void cp_async16(uint32_t dst, const void* src, int src_bytes) {
    asm volatile("cp.async.cg.shared.global [%0], [%1], 16, %2;"
                 :: "r"(dst), "l"(src), "r"(src_bytes) : "memory");
}

// ---------------- sort / gather ----------------
__global__ void k_sort(const int* __restrict__ caplen, const int* __restrict__ caps,
                       float* __restrict__ out, long long out_size) {
    __shared__ int lens[BB];
    int b = threadIdx.x;
    lens[b] = caplen[b];
    if (b == 0) g_bar = 0u;
    __syncthreads();
    int my = lens[b];
    int rank = 0;
    for (int j = 0; j < BB; j++) {
        int lj = lens[j];
        if (lj > my || (lj == my && j < b)) rank++;
    }
    g_sort[rank] = b;
    __syncthreads();
    int s = g_sort[b];
    int dl = lens[s] - 1;
    g_declen[b] = dl;
    for (int l = 0; l < LLEN; l++) g_capsS[b * LLEN + l] = caps[s * LLEN + l];
    for (int t = 0; t < TT; t++)   g_rowmap[b * TT + t] = g_capsS[b * LLEN + t];
    for (int d = 0; d < DD; d++)   g_c[b * DD + d] = 0.0f;
    long long off = (long long)MROWS * VV;
    if (out_size >= off + (long long)BB * LLEN + 2 * BB) {
        for (int l = 0; l < LLEN; l++) out[off + b * LLEN + l] = (float)g_capsS[b * LLEN + l];
        out[off + (long long)BB * LLEN + b]      = (float)dl;
        out[off + (long long)BB * LLEN + BB + b] = (float)s;
    }
}

// ---------------- mean features ----------------
__global__ __launch_bounds__(256) void k_mean(const float* __restrict__ img) {
    int p = blockIdx.x;
    int s = g_sort[p];
    const float* base = img + (long long)s * NPP * FEATN;
    int f0 = threadIdx.x;
    float acc[8] = {0,0,0,0,0,0,0,0};
    for (int q = 0; q < NPP; q++) {
        const float* rowp = base + (long long)q * FEATN;
        #pragma unroll
        for (int u = 0; u < 8; u++) acc[u] += rowp[f0 + u * 256];
    }
    #pragma unroll
    for (int u = 0; u < 8; u++)
        g_feats[(long long)p * FEATN + f0 + u * 256] = acc[u] * (1.0f / 196.0f);
}

// ---------------- SIMT GEMM (small h0 only) ----------------
template<int BM, int BN, int BK, int TM, int TN>
__global__ __launch_bounds__((BM/TM)*(BN/TN)) void gemm_nt(
    const float* __restrict__ A, int lda,
    const float* __restrict__ B, int ldb,
    const float* __restrict__ bias1,
    float* __restrict__ C, int ldc, int K)
{
    constexpr int NT = (BM / TM) * (BN / TN);
    __shared__ float As[BK][BM + 4];
    __shared__ float Bs[BK][BN + 4];
    const int tid = threadIdx.x;
    const int tx = tid % (BN / TN);
    const int ty = tid / (BN / TN);
    const int row0 = blockIdx.y * BM;
    const int col0 = blockIdx.x * BN;

    float acc[TM][TN];
    #pragma unroll
    for (int i = 0; i < TM; i++)
        #pragma unroll
        for (int j = 0; j < TN; j++) acc[i][j] = 0.0f;

    for (int k0 = 0; k0 < K; k0 += BK) {
        for (int e = tid; e < BM * BK; e += NT) {
            int r = e / BK, k = e % BK;
            As[k][r] = A[(long long)(row0 + r) * lda + k0 + k];
        }
        for (int e = tid; e < BN * BK; e += NT) {
            int c = e / BK, k = e % BK;
            Bs[k][c] = B[(long long)(col0 + c) * ldb + k0 + k];
        }
        __syncthreads();
        #pragma unroll
        for (int kk = 0; kk < BK; kk++) {
            float ra[TM], rb[TN];
            #pragma unroll
            for (int i = 0; i < TM; i += 4) {
                float4 v = *reinterpret_cast<const float4*>(&As[kk][ty * TM + i]);
                ra[i] = v.x; ra[i+1] = v.y; ra[i+2] = v.z; ra[i+3] = v.w;
            }
            #pragma unroll
            for (int j = 0; j < TN; j += 4) {
                float4 v = *reinterpret_cast<const float4*>(&Bs[kk][tx * TN + j]);
                rb[j] = v.x; rb[j+1] = v.y; rb[j+2] = v.z; rb[j+3] = v.w;
            }
            #pragma unroll
            for (int i = 0; i < TM; i++)
                #pragma unroll
                for (int j = 0; j < TN; j++)
                    acc[i][j] += ra[i] * rb[j];
        }
        __syncthreads();
    }
    #pragma unroll
    for (int i = 0; i < TM; i++) {
        int gr = row0 + ty * TM + i;
        #pragma unroll
        for (int j = 0; j < TN; j++) {
            int gc = col0 + tx * TN + j;
            C[(long long)gr * ldc + gc] = acc[i][j] + bias1[gc];
        }
    }
}

// ---------------- bf16 split helpers ----------------
__device__ __forceinline__ void split2(float a, float b, uint32_t& h, uint32_t& l) {
    __nv_bfloat16 ha = __float2bfloat16(a);
    __nv_bfloat16 hb = __float2bfloat16(b);
    float ra = a - __bfloat162float(ha);
    float rb = b - __bfloat162float(hb);
    __nv_bfloat16 la = __float2bfloat16(ra);
    __nv_bfloat16 lb = __float2bfloat16(rb);
    h = ((uint32_t)__bfloat16_as_ushort(hb) << 16) | (uint32_t)__bfloat16_as_ushort(ha);
    l = ((uint32_t)__bfloat16_as_ushort(lb) << 16) | (uint32_t)__bfloat16_as_ushort(la);
}

__global__ __launch_bounds__(256) void k_split(const float4* __restrict__ src,
                                               uint2* __restrict__ hi, uint2* __restrict__ lo, int n4) {
    int i = blockIdx.x * 256 + threadIdx.x;
    if (i >= n4) return;
    float4 v = src[i];
    uint2 h, l;
    split2(v.x, v.y, h.x, l.x);
    split2(v.z, v.w, h.y, l.y);
    hi[i] = h;
    lo[i] = l;
}

__global__ __launch_bounds__(128) void k_split_emb(const float* __restrict__ emb) {
    int m = blockIdx.x;
    int tok = g_rowmap[m];
    float4 v = reinterpret_cast<const float4*>(emb + (long long)tok * EE)[threadIdx.x];
    uint2 h, l;
    split2(v.x, v.y, h.x, l.x);
    split2(v.z, v.w, h.y, l.y);
    reinterpret_cast<uint2*>(g_Ahi + (long long)m * KK)[threadIdx.x] = h;
    reinterpret_cast<uint2*>(g_Alo + (long long)m * KK)[threadIdx.x] = l;
}

// ---------------- mma.sync bf16 3-pass split GEMM (cp.async double-buffered) ----------------
#define MG_TILE_ELEMS (128 * 40)
#define MG_STAGE_BYTES (4 * MG_TILE_ELEMS * 2)
#define MG_SMEM (2 * MG_STAGE_BYTES)

template<int MODE>
__global__ __launch_bounds__(256)
void mma_gemm(const __nv_bfloat16* __restrict__ Ahi, const __nv_bfloat16* __restrict__ Alo,
              const __nv_bfloat16* __restrict__ Bhi, const __nv_bfloat16* __restrict__ Blo,
              const float* __restrict__ bias1, const float* __restrict__ bias2,
              float* __restrict__ C, int ldc, int Ncols,
              const int* __restrict__ declen)
{
    extern __shared__ __align__(16) __nv_bfloat16 smp[];
    const int tid  = threadIdx.x;
    const int lane = tid & 31;
    const int w    = tid >> 5;
    const int wm   = w >> 1;
    const int wn   = w & 1;
    const int row0 = blockIdx.y * 128;
    const int col0 = blockIdx.x * 128;
    const int mat  = lane >> 3;
    const int mr   = lane & 7;

    float acc[2][8][4];
    #pragma unroll
    for (int i = 0; i < 2; i++)
        #pragma unroll
        for (int j = 0; j < 8; j++)
            #pragma unroll
            for (int q = 0; q < 4; q++) acc[i][j][q] = 0.0f;

    auto stage_load = [&](int ch, int buf) {
        const int k0 = ch * 32;
        __nv_bfloat16* base = smp + (size_t)buf * 4 * MG_TILE_ELEMS;
        #pragma unroll
        for (int e = tid; e < 2048; e += 256) {
            int tsel = e >> 9;
            int i = e & 511;
            int r = i >> 2, q = i & 3;
            const __nv_bfloat16* src;
            int sz = 16;
            if (tsel < 2) {
                src = (tsel == 0 ? Ahi : Alo) + (size_t)(row0 + r) * KK + k0 + q * 8;
            } else {
                int gc = col0 + r;
                int gcs = (gc < Ncols) ? gc : 0;
                src = (tsel == 2 ? Bhi : Blo) + (size_t)gcs * KK + k0 + q * 8;
                sz = (gc < Ncols) ? 16 : 0;
            }
            cp_async16(smem_u32(base + tsel * MG_TILE_ELEMS + r * 40 + q * 8), src, sz);
        }
        asm volatile("cp.async.commit_group;" ::: "memory");
    };

    stage_load(0, 0);

    for (int ch = 0; ch < 16; ch++) {
        if (ch + 1 < 16) {
            stage_load(ch + 1, (ch + 1) & 1);
            asm volatile("cp.async.wait_group 1;" ::: "memory");
        } else {
            asm volatile("cp.async.wait_group 0;" ::: "memory");
        }
        __syncthreads();

        const uint32_t sbase = smem_u32(smp) + (uint32_t)((ch & 1) * MG_STAGE_BYTES);
        const uint32_t sA0 = sbase;
        const uint32_t sA1 = sbase + MG_TILE_ELEMS * 2;
        const uint32_t sB0 = sbase + MG_TILE_ELEMS * 4;
        const uint32_t sB1 = sbase + MG_TILE_ELEMS * 6;

        #pragma unroll
        for (int kk = 0; kk < 32; kk += 16) {
            uint32_t ahi[2][4], alo[2][4], bhi[8][2], blo[8][2];
            const int acol = kk + ((mat >> 1) << 3);
            const int bcolA = kk + ((mat & 1) << 3);
            #pragma unroll
            for (int mi = 0; mi < 2; mi++) {
                int rrow = wm * 32 + mi * 16 + mr + ((mat & 1) << 3);
                ldsm_x4(ahi[mi], sA0 + (uint32_t)(rrow * 40 + acol) * 2);
            }
            #pragma unroll
            for (int j2 = 0; j2 < 4; j2++) {
                int nrow = wn * 64 + j2 * 16 + mr + ((mat >> 1) << 3);
                uint32_t r4[4];
                ldsm_x4(r4, sB0 + (uint32_t)(nrow * 40 + bcolA) * 2);
                bhi[2*j2][0] = r4[0]; bhi[2*j2][1] = r4[1];
                bhi[2*j2+1][0] = r4[2]; bhi[2*j2+1][1] = r4[3];
            }
            #pragma unroll
            for (int mi = 0; mi < 2; mi++)
                #pragma unroll
                for (int j = 0; j < 8; j++)
                    mma_bf16(acc[mi][j], ahi[mi], bhi[j]);
            #pragma unroll
            for (int j2 = 0; j2 < 4; j2++) {
                int nrow = wn * 64 + j2 * 16 + mr + ((mat >> 1) << 3);
                uint32_t r4[4];
                ldsm_x4(r4, sB1 + (uint32_t)(nrow * 40 + bcolA) * 2);
                blo[2*j2][0] = r4[0]; blo[2*j2][1] = r4[1];
                blo[2*j2+1][0] = r4[2]; blo[2*j2+1][1] = r4[3];
            }
            #pragma unroll
            for (int mi = 0; mi < 2; mi++)
                #pragma unroll
                for (int j = 0; j < 8; j++)
                    mma_bf16(acc[mi][j], ahi[mi], blo[j]);
            #pragma unroll
            for (int mi = 0; mi < 2; mi++) {
                int rrow = wm * 32 + mi * 16 + mr + ((mat & 1) << 3);
                ldsm_x4(alo[mi], sA1 + (uint32_t)(rrow * 40 + acol) * 2);
            }
            #pragma unroll
            for (int mi = 0; mi < 2; mi++)
                #pragma unroll
                for (int j = 0; j < 8; j++)
                    mma_bf16(acc[mi][j], alo[mi], bhi[j]);
        }
        __syncthreads();
    }

    #pragma unroll
    for (int mi = 0; mi < 2; mi++) {
        int gr0 = row0 + wm * 32 + mi * 16 + (lane >> 2);
        float m0 = 1.0f, m1 = 1.0f;
        if (MODE == 2) {
            int b0 = gr0 / TT,       t0 = gr0 - b0 * TT;
            int b1 = (gr0 + 8) / TT, t1 = (gr0 + 8) - b1 * TT;
            m0 = (t0 < declen[b0]) ? 1.0f : 0.0f;
            m1 = (t1 < declen[b1]) ? 1.0f : 0.0f;
        }
        #pragma unroll
        for (int j = 0; j < 8; j++) {
            int gc = col0 + wn * 64 + j * 8 + ((lane & 3) << 1);
            if (gc + 1 < Ncols) {
                float bi0 = bias1[gc], bi1 = bias1[gc + 1];
                if (MODE == 0 && bias2) { bi0 += bias2[gc]; bi1 += bias2[gc + 1]; }
                float2 v0 = make_float2((acc[mi][j][0] + bi0) * m0, (acc[mi][j][1] + bi1) * m0);
                float2 v1 = make_float2((acc[mi][j][2] + bi0) * m1, (acc[mi][j][3] + bi1) * m1);
                *reinterpret_cast<float2*>(&C[(size_t)gr0 * ldc + gc]) = v0;
                *reinterpret_cast<float2*>(&C[(size_t)(gr0 + 8) * ldc + gc]) = v1;
            } else if (gc < Ncols) {
                float bi0 = bias1[gc];
                if (MODE == 0 && bias2) bi0 += bias2[gc];
                C[(size_t)gr0 * ldc + gc]       = (acc[mi][j][0] + bi0) * m0;
                C[(size_t)(gr0 + 8) * ldc + gc] = (acc[mi][j][2] + bi0) * m1;
            }
        }
    }
}

// ---------------- persistent LSTM recurrence (f32x2 + pipelined hin loads) ----------------
#define RSW_STRIDE 514
#define RSH_STRIDE 130
#define SH_BUF (64 * RSH_STRIDE)
#define RSG_STRIDE 20
#define RSMEM_BYTES ((16*RSW_STRIDE + 2*SH_BUF + 128*RSG_STRIDE) * 4)

__global__ __launch_bounds__(256)
void k_recur(const float* __restrict__ w_hh) {
    extern __shared__ float smr[];
    float* sW = smr;                         // [16][514]
    float* sH = sW + 16 * RSW_STRIDE;        // [2][64][130]
    float* sG = sH + 2 * SH_BUF;             // [128][20]
    const int tid = threadIdx.x;
    const int cid = blockIdx.x;
    const int g   = tid & 15;
    const int bg  = tid >> 4;
    const int b0  = bg * 8;
    const int lb  = tid >> 6;                // load decomposition: b = lb + 4*i
    const int lk  = tid & 63;                // kloc within block

    for (int e = tid; e < 16 * 512; e += 256) {
        int gg = e >> 9, k = e & 511;
        int row = ((gg >> 2) << 9) + cid * 4 + (gg & 3);
        sW[gg * RSW_STRIDE + k] = w_hh[(size_t)row * DD + k];
    }
    const int colg = ((g >> 2) << 9) + cid * 4 + (g & 3);

    for (int t = 0; t < TT; t++) {
        const float* hin  = g_hbuf[t & 1];
        float*       hout = g_hbuf[(t + 1) & 1];
        float tmp[32];

        // preload kb block 0 (max MLP: all 32 LDGs issued before any STS)
        #pragma unroll
        for (int i = 0; i < 32; i++)
            tmp[i] = __ldcg(&hin[(lb + 4 * i) * DD + lk]);
        #pragma unroll
        for (int i = 0; i < 32; i++)
            sH[lk * RSH_STRIDE + lb + 4 * i] = tmp[i];
        __syncthreads();

        unsigned long long accp[4] = {0ull, 0ull, 0ull, 0ull};

        for (int kbi = 0; kbi < 8; kbi++) {
            const int kb = kbi * 64;
            // issue next block's loads before compute so they overlap
            if (kbi + 1 < 8) {
                #pragma unroll
                for (int i = 0; i < 32; i++)
                    tmp[i] = __ldcg(&hin[(lb + 4 * i) * DD + kb + 64 + lk]);
            }
            const float* wrow = sW + g * RSW_STRIDE + kb;
            const float* hrow = sH + (kbi & 1) * SH_BUF + b0;
            #pragma unroll 8
            for (int kloc = 0; kloc < 64; kloc++) {
                unsigned int wu = __float_as_uint(wrow[kloc]);
                unsigned long long wp;
                asm("mov.b64 %0, {%1, %1};" : "=l"(wp) : "r"(wu));
                const unsigned long long* hp =
                    (const unsigned long long*)(hrow + kloc * RSH_STRIDE);
                asm("fma.rn.f32x2 %0, %1, %2, %0;" : "+l"(accp[0]) : "l"(hp[0]), "l"(wp));
                asm("fma.rn.f32x2 %0, %1, %2, %0;" : "+l"(accp[1]) : "l"(hp[1]), "l"(wp));
                asm("fma.rn.f32x2 %0, %1, %2, %0;" : "+l"(accp[2]) : "l"(hp[2]), "l"(wp));
                asm("fma.rn.f32x2 %0, %1, %2, %0;" : "+l"(accp[3]) : "l"(hp[3]), "l"(wp));
            }
            if (kbi + 1 < 8) {
                #pragma unroll
                for (int i = 0; i < 32; i++)
                    sH[((kbi + 1) & 1) * SH_BUF + lk * RSH_STRIDE + lb + 4 * i] = tmp[i];
            }
            __syncthreads();
        }

        // unpack and exchange through sG
        float acc[8];
        #pragma unroll
        for (int q = 0; q < 4; q++) {
            acc[2*q]   = __uint_as_float((unsigned)(accp[q] & 0xffffffffull));
            acc[2*q+1] = __uint_as_float((unsigned)(accp[q] >> 32));
        }
        #pragma unroll
        for (int i = 0; i < 8; i++) {
            int b = b0 + i;
            sG[b * RSG_STRIDE + g] = acc[i] + g_X[(size_t)(b * TT + t) * G4 + colg];
        }
        __syncthreads();
        #pragma unroll
        for (int e = tid; e < 512; e += 256) {
            int b = e >> 2, dl = e & 3;
            float gi = sG[b * RSG_STRIDE + dl];
            float gf = sG[b * RSG_STRIDE + 4 + dl];
            float gg = sG[b * RSG_STRIDE + 8 + dl];
            float go = sG[b * RSG_STRIDE + 12 + dl];
            float si = 1.0f / (1.0f + expf(-gi));
            float sf = 1.0f / (1.0f + expf(-gf));
            float tg = tanhf(gg);
            float so = 1.0f / (1.0f + expf(-go));
            int d = cid * 4 + dl;
            float cold = g_c[b * DD + d];
            float cnew = sf * cold + si * tg;
            float hnew = so * tanhf(cnew);
            g_H[(size_t)(b * TT + t) * DD + d] = hnew;
            bool m = t < g_declen[b];
            hout[b * DD + d] = m ? hnew : __ldcg(&hin[b * DD + d]);
            if (m) g_c[b * DD + d] = cnew;
        }
        __threadfence();
        __syncthreads();
        if (tid == 0) {
            atomicAdd(&g_bar, 1u);
            unsigned target = (unsigned)(128 * (t + 1));
            unsigned v;
            do {
                asm volatile("ld.acquire.gpu.u32 %0, [%1];" : "=r"(v) : "l"(&g_bar));
            } while (v < target);
        }
        __syncthreads();
    }
}

// ---------------- launch (reordered so mma_gemm<0> sits in the ncu profiled slot) ----------------
extern "C" void kernel_launch(void* const* d_in, const int* in_sizes, int n_in,
                              void* d_out, int out_size) {
    const float* img    = (const float*)d_in[0];
    const int*   caps   = (const int*)  d_in[1];
    const int*   caplen = (const int*)  d_in[2];
    const float* embtab = (const float*)d_in[3];
    const float* att1_w = (const float*)d_in[4];
    const float* att1_b = (const float*)d_in[5];
    const float* w_ih   = (const float*)d_in[6];
    const float* w_hh   = (const float*)d_in[7];
    const float* b_ih   = (const float*)d_in[8];
    const float* b_hh   = (const float*)d_in[9];
    const float* word_w = (const float*)d_in[10];
    const float* word_b = (const float*)d_in[11];
    float* out = (float*)d_out;

    float *pX, *pH, *pFeats, *pHbuf;
    __nv_bfloat16 *pAhi, *pAlo, *pBhi, *pBlo;
    int *pDeclen;
    cudaGetSymbolAddress((void**)&pX,     g_X);
    cudaGetSymbolAddress((void**)&pH,     g_H);
    cudaGetSymbolAddress((void**)&pFeats, g_feats);
    cudaGetSymbolAddress((void**)&pHbuf,  g_hbuf);
    cudaGetSymbolAddress((void**)&pAhi,   g_Ahi);
    cudaGetSymbolAddress((void**)&pAlo,   g_Alo);
    cudaGetSymbolAddress((void**)&pBhi,   g_Bhi);
    cudaGetSymbolAddress((void**)&pBlo,   g_Blo);
    cudaGetSymbolAddress((void**)&pDeclen,g_declen);

    cudaFuncSetAttribute(k_recur, cudaFuncAttributeMaxDynamicSharedMemorySize, RSMEM_BYTES);
    cudaFuncSetAttribute(mma_gemm<0>, cudaFuncAttributeMaxDynamicSharedMemorySize, MG_SMEM);
    cudaFuncSetAttribute(mma_gemm<2>, cudaFuncAttributeMaxDynamicSharedMemorySize, MG_SMEM);

    // 0) sort / gather / tail outputs / zero c & barrier
    k_sort<<<1, BB>>>(caplen, caps, out, (long long)out_size);
    // 1) split w_ih
    k_split<<<(G4 * KK / 4 + 255) / 256, 256>>>((const float4*)w_ih, (uint2*)pBhi, (uint2*)pBlo, G4 * KK / 4);
    // 2) gather+split emb (needs rowmap from k_sort)
    k_split_emb<<<MROWS, 128>>>(embtab);
    // 3) X = emb @ w_ih^T + b_ih + b_hh  (HMMA)  <- ncu profiled slot
    {
        dim3 grid(G4 / 128, MROWS / 128);
        mma_gemm<0><<<grid, 256, MG_SMEM>>>(pAhi, pAlo, pBhi, pBlo, b_ih, b_hh, pX, G4, G4, nullptr);
    }
    // 4) mean features (sorted)
    k_mean<<<BB, 256>>>(img);
    // 5) h0 = feats @ att1_w^T + att1_b
    {
        dim3 grid(DD / 64, BB / 64);
        gemm_nt<64, 64, 16, 4, 4><<<grid, 256>>>(
            pFeats, FEATN, att1_w, FEATN, att1_b, pHbuf, DD, FEATN);
    }
    // 6) persistent recurrence
    k_recur<<<128, 256, RSMEM_BYTES>>>(w_hh);
    // 7) split H and word_w
    k_split<<<(MROWS * DD / 4 + 255) / 256, 256>>>((const float4*)pH, (uint2*)pAhi, (uint2*)pAlo, MROWS * DD / 4);
    k_split<<<(VV * KK / 4 + 255) / 256, 256>>>((const float4*)word_w, (uint2*)pBhi, (uint2*)pBlo, VV * KK / 4);
    // 8) predictions = mask * (H @ word_w^T + word_b)  (HMMA)
    {
        dim3 grid((VV + 127) / 128, MROWS / 128);
        mma_gemm<2><<<grid, 256, MG_SMEM>>>(pAhi, pAlo, pBhi, pBlo, word_b, nullptr, out, VV, VV, pDeclen);
    }
}

// round 12
// speedup vs baseline: 2.5727x; 1.3978x over previous
#include <cuda_runtime.h>
#include <cuda_bf16.h>
#include <cstdint>
#include <math.h>

// Problem constants
#define BB   128
#define LLEN 52
#define TT   51
#define EE   512
#define DD   512
#define VV   10000
#define FEATN 2048
#define NPP  196
#define G4   2048
#define KK   512
#define MROWS (BB*TT)        // 6528

// ---------------- scratch ----------------
__device__ float g_X[(size_t)MROWS * G4];
__device__ float g_feats[(size_t)BB * FEATN];
__device__ float g_hbuf[BB * DD];            // h0 fp32 staging
__device__ float g_c[BB * DD];
__device__ int   g_sort[BB];
__device__ int   g_declen[BB];
__device__ int   g_capsS[BB * LLEN];
__device__ int   g_rowmap[MROWS];
__device__ unsigned g_bar;
// h state in bf16 hi/lo split, ping-pong
__device__ __nv_bfloat16 g_hHi[2][BB * DD];
__device__ __nv_bfloat16 g_hLo[2][BB * DD];
// bf16 split buffers (A: emb-gather then H-history; B: w_ih, then w_hh, then word_w)
__device__ __nv_bfloat16 g_Ahi[(size_t)MROWS * KK];
__device__ __nv_bfloat16 g_Alo[(size_t)MROWS * KK];
__device__ __nv_bfloat16 g_Bhi[(size_t)VV * KK];
__device__ __nv_bfloat16 g_Blo[(size_t)VV * KK];

// ---------------- small helpers ----------------
__device__ __forceinline__ uint32_t smem_u32(const void* p) {
    return (uint32_t)__cvta_generic_to_shared(p);
}
__device__ __forceinline__ void ldsm_x4(uint32_t* r, uint32_t addr) {
    asm volatile("ldmatrix.sync.aligned.m8n8.x4.shared.b16 {%0,%1,%2,%3}, [%4];"
                 : "=r"(r[0]), "=r"(r[1]), "=r"(r[2]), "=r"(r[3]) : "r"(addr));
}
__device__ __forceinline__ void mma_bf16(float* c, const uint32_t* a, const uint32_t* b) {
    asm volatile("mma.sync.aligned.m16n8k16.row.col.f32.bf16.bf16.f32 "
                 "{%0,%1,%2,%3},{%4,%5,%6,%7},{%8,%9},{%0,%1,%2,%3};"
                 : "+f"(c[0]), "+f"(c[1]), "+f"(c[2]), "+f"(c[3])
                 : "r"(a[0]), "r"(a[1]), "r"(a[2]), "r"(a[3]), "r"(b[0]), "r"(b[1]));
}
__device__ __forceinline__ void cp_async16(uint32_t dst, const void* src, int src_bytes) {
    asm volatile("cp.async.cg.shared.global [%0], [%1], 16, %2;"
                 :: "r"(dst), "l"(src), "r"(src_bytes) : "memory");
}

// ---------------- sort / gather ----------------
__global__ void k_sort(const int* __restrict__ caplen, const int* __restrict__ caps,
                       float* __restrict__ out, long long out_size) {
    __shared__ int lens[BB];
    int b = threadIdx.x;
    lens[b] = caplen[b];
    if (b == 0) g_bar = 0u;
    __syncthreads();
    int my = lens[b];
    int rank = 0;
    for (int j = 0; j < BB; j++) {
        int lj = lens[j];
        if (lj > my || (lj == my && j < b)) rank++;
    }
    g_sort[rank] = b;
    __syncthreads();
    int s = g_sort[b];
    int dl = lens[s] - 1;
    g_declen[b] = dl;
    for (int l = 0; l < LLEN; l++) g_capsS[b * LLEN + l] = caps[s * LLEN + l];
    for (int t = 0; t < TT; t++)   g_rowmap[b * TT + t] = g_capsS[b * LLEN + t];
    for (int d = 0; d < DD; d++)   g_c[b * DD + d] = 0.0f;
    long long off = (long long)MROWS * VV;
    if (out_size >= off + (long long)BB * LLEN + 2 * BB) {
        for (int l = 0; l < LLEN; l++) out[off + b * LLEN + l] = (float)g_capsS[b * LLEN + l];
        out[off + (long long)BB * LLEN + b]      = (float)dl;
        out[off + (long long)BB * LLEN + BB + b] = (float)s;
    }
}

// ---------------- mean features ----------------
__global__ __launch_bounds__(256) void k_mean(const float* __restrict__ img) {
    int p = blockIdx.x;
    int s = g_sort[p];
    const float* base = img + (long long)s * NPP * FEATN;
    int f0 = threadIdx.x;
    float acc[8] = {0,0,0,0,0,0,0,0};
    for (int q = 0; q < NPP; q++) {
        const float* rowp = base + (long long)q * FEATN;
        #pragma unroll
        for (int u = 0; u < 8; u++) acc[u] += rowp[f0 + u * 256];
    }
    #pragma unroll
    for (int u = 0; u < 8; u++)
        g_feats[(long long)p * FEATN + f0 + u * 256] = acc[u] * (1.0f / 196.0f);
}

// ---------------- SIMT GEMM (small h0 only) ----------------
template<int BM, int BN, int BK, int TM, int TN>
__global__ __launch_bounds__((BM/TM)*(BN/TN)) void gemm_nt(
    const float* __restrict__ A, int lda,
    const float* __restrict__ B, int ldb,
    const float* __restrict__ bias1,
    float* __restrict__ C, int ldc, int K)
{
    constexpr int NT = (BM / TM) * (BN / TN);
    __shared__ float As[BK][BM + 4];
    __shared__ float Bs[BK][BN + 4];
    const int tid = threadIdx.x;
    const int tx = tid % (BN / TN);
    const int ty = tid / (BN / TN);
    const int row0 = blockIdx.y * BM;
    const int col0 = blockIdx.x * BN;

    float acc[TM][TN];
    #pragma unroll
    for (int i = 0; i < TM; i++)
        #pragma unroll
        for (int j = 0; j < TN; j++) acc[i][j] = 0.0f;

    for (int k0 = 0; k0 < K; k0 += BK) {
        for (int e = tid; e < BM * BK; e += NT) {
            int r = e / BK, k = e % BK;
            As[k][r] = A[(long long)(row0 + r) * lda + k0 + k];
        }
        for (int e = tid; e < BN * BK; e += NT) {
            int c = e / BK, k = e % BK;
            Bs[k][c] = B[(long long)(col0 + c) * ldb + k0 + k];
        }
        __syncthreads();
        #pragma unroll
        for (int kk = 0; kk < BK; kk++) {
            float ra[TM], rb[TN];
            #pragma unroll
            for (int i = 0; i < TM; i += 4) {
                float4 v = *reinterpret_cast<const float4*>(&As[kk][ty * TM + i]);
                ra[i] = v.x; ra[i+1] = v.y; ra[i+2] = v.z; ra[i+3] = v.w;
            }
            #pragma unroll
            for (int j = 0; j < TN; j += 4) {
                float4 v = *reinterpret_cast<const float4*>(&Bs[kk][tx * TN + j]);
                rb[j] = v.x; rb[j+1] = v.y; rb[j+2] = v.z; rb[j+3] = v.w;
            }
            #pragma unroll
            for (int i = 0; i < TM; i++)
                #pragma unroll
                for (int j = 0; j < TN; j++)
                    acc[i][j] += ra[i] * rb[j];
        }
        __syncthreads();
    }
    #pragma unroll
    for (int i = 0; i < TM; i++) {
        int gr = row0 + ty * TM + i;
        #pragma unroll
        for (int j = 0; j < TN; j++) {
            int gc = col0 + tx * TN + j;
            C[(long long)gr * ldc + gc] = acc[i][j] + bias1[gc];
        }
    }
}

// ---------------- bf16 split helpers ----------------
__device__ __forceinline__ void split2(float a, float b, uint32_t& h, uint32_t& l) {
    __nv_bfloat16 ha = __float2bfloat16(a);
    __nv_bfloat16 hb = __float2bfloat16(b);
    float ra = a - __bfloat162float(ha);
    float rb = b - __bfloat162float(hb);
    __nv_bfloat16 la = __float2bfloat16(ra);
    __nv_bfloat16 lb = __float2bfloat16(rb);
    h = ((uint32_t)__bfloat16_as_ushort(hb) << 16) | (uint32_t)__bfloat16_as_ushort(ha);
    l = ((uint32_t)__bfloat16_as_ushort(lb) << 16) | (uint32_t)__bfloat16_as_ushort(la);
}

__global__ __launch_bounds__(256) void k_split(const float4* __restrict__ src,
                                               uint2* __restrict__ hi, uint2* __restrict__ lo, int n4) {
    int i = blockIdx.x * 256 + threadIdx.x;
    if (i >= n4) return;
    float4 v = src[i];
    uint2 h, l;
    split2(v.x, v.y, h.x, l.x);
    split2(v.z, v.w, h.y, l.y);
    hi[i] = h;
    lo[i] = l;
}

__global__ __launch_bounds__(128) void k_split_emb(const float* __restrict__ emb) {
    int m = blockIdx.x;
    int tok = g_rowmap[m];
    float4 v = reinterpret_cast<const float4*>(emb + (long long)tok * EE)[threadIdx.x];
    uint2 h, l;
    split2(v.x, v.y, h.x, l.x);
    split2(v.z, v.w, h.y, l.y);
    reinterpret_cast<uint2*>(g_Ahi + (long long)m * KK)[threadIdx.x] = h;
    reinterpret_cast<uint2*>(g_Alo + (long long)m * KK)[threadIdx.x] = l;
}

// ---------------- mma.sync bf16 3-pass split GEMM (cp.async double-buffered) ----------------
#define MG_TILE_ELEMS (128 * 40)
#define MG_STAGE_BYTES (4 * MG_TILE_ELEMS * 2)
#define MG_SMEM (2 * MG_STAGE_BYTES)

template<int MODE>
__global__ __launch_bounds__(256)
void mma_gemm(const __nv_bfloat16* __restrict__ Ahi, const __nv_bfloat16* __restrict__ Alo,
              const __nv_bfloat16* __restrict__ Bhi, const __nv_bfloat16* __restrict__ Blo,
              const float* __restrict__ bias1, const float* __restrict__ bias2,
              float* __restrict__ C, int ldc, int Ncols,
              const int* __restrict__ declen)
{
    extern __shared__ __align__(16) __nv_bfloat16 smp[];
    const int tid  = threadIdx.x;
    const int lane = tid & 31;
    const int w    = tid >> 5;
    const int wm   = w >> 1;
    const int wn   = w & 1;
    const int row0 = blockIdx.y * 128;
    const int col0 = blockIdx.x * 128;
    const int mat  = lane >> 3;
    const int mr   = lane & 7;

    float acc[2][8][4];
    #pragma unroll
    for (int i = 0; i < 2; i++)
        #pragma unroll
        for (int j = 0; j < 8; j++)
            #pragma unroll
            for (int q = 0; q < 4; q++) acc[i][j][q] = 0.0f;

    auto stage_load = [&](int ch, int buf) {
        const int k0 = ch * 32;
        __nv_bfloat16* base = smp + (size_t)buf * 4 * MG_TILE_ELEMS;
        #pragma unroll
        for (int e = tid; e < 2048; e += 256) {
            int tsel = e >> 9;
            int i = e & 511;
            int r = i >> 2, q = i & 3;
            const __nv_bfloat16* src;
            int sz = 16;
            if (tsel < 2) {
                src = (tsel == 0 ? Ahi : Alo) + (size_t)(row0 + r) * KK + k0 + q * 8;
            } else {
                int gc = col0 + r;
                int gcs = (gc < Ncols) ? gc : 0;
                src = (tsel == 2 ? Bhi : Blo) + (size_t)gcs * KK + k0 + q * 8;
                sz = (gc < Ncols) ? 16 : 0;
            }
            cp_async16(smem_u32(base + tsel * MG_TILE_ELEMS + r * 40 + q * 8), src, sz);
        }
        asm volatile("cp.async.commit_group;" ::: "memory");
    };

    stage_load(0, 0);

    for (int ch = 0; ch < 16; ch++) {
        if (ch + 1 < 16) {
            stage_load(ch + 1, (ch + 1) & 1);
            asm volatile("cp.async.wait_group 1;" ::: "memory");
        } else {
            asm volatile("cp.async.wait_group 0;" ::: "memory");
        }
        __syncthreads();

        const uint32_t sbase = smem_u32(smp) + (uint32_t)((ch & 1) * MG_STAGE_BYTES);
        const uint32_t sA0 = sbase;
        const uint32_t sA1 = sbase + MG_TILE_ELEMS * 2;
        const uint32_t sB0 = sbase + MG_TILE_ELEMS * 4;
        const uint32_t sB1 = sbase + MG_TILE_ELEMS * 6;

        #pragma unroll
        for (int kk = 0; kk < 32; kk += 16) {
            uint32_t ahi[2][4], alo[2][4], bhi[8][2], blo[8][2];
            const int acol = kk + ((mat >> 1) << 3);
            const int bcolA = kk + ((mat & 1) << 3);
            #pragma unroll
            for (int mi = 0; mi < 2; mi++) {
                int rrow = wm * 32 + mi * 16 + mr + ((mat & 1) << 3);
                ldsm_x4(ahi[mi], sA0 + (uint32_t)(rrow * 40 + acol) * 2);
            }
            #pragma unroll
            for (int j2 = 0; j2 < 4; j2++) {
                int nrow = wn * 64 + j2 * 16 + mr + ((mat >> 1) << 3);
                uint32_t r4[4];
                ldsm_x4(r4, sB0 + (uint32_t)(nrow * 40 + bcolA) * 2);
                bhi[2*j2][0] = r4[0]; bhi[2*j2][1] = r4[1];
                bhi[2*j2+1][0] = r4[2]; bhi[2*j2+1][1] = r4[3];
            }
            #pragma unroll
            for (int mi = 0; mi < 2; mi++)
                #pragma unroll
                for (int j = 0; j < 8; j++)
                    mma_bf16(acc[mi][j], ahi[mi], bhi[j]);
            #pragma unroll
            for (int j2 = 0; j2 < 4; j2++) {
                int nrow = wn * 64 + j2 * 16 + mr + ((mat >> 1) << 3);
                uint32_t r4[4];
                ldsm_x4(r4, sB1 + (uint32_t)(nrow * 40 + bcolA) * 2);
                blo[2*j2][0] = r4[0]; blo[2*j2][1] = r4[1];
                blo[2*j2+1][0] = r4[2]; blo[2*j2+1][1] = r4[3];
            }
            #pragma unroll
            for (int mi = 0; mi < 2; mi++)
                #pragma unroll
                for (int j = 0; j < 8; j++)
                    mma_bf16(acc[mi][j], ahi[mi], blo[j]);
            #pragma unroll
            for (int mi = 0; mi < 2; mi++) {
                int rrow = wm * 32 + mi * 16 + mr + ((mat & 1) << 3);
                ldsm_x4(alo[mi], sA1 + (uint32_t)(rrow * 40 + acol) * 2);
            }
            #pragma unroll
            for (int mi = 0; mi < 2; mi++)
                #pragma unroll
                for (int j = 0; j < 8; j++)
                    mma_bf16(acc[mi][j], alo[mi], bhi[j]);
        }
        __syncthreads();
    }

    #pragma unroll
    for (int mi = 0; mi < 2; mi++) {
        int gr0 = row0 + wm * 32 + mi * 16 + (lane >> 2);
        float m0 = 1.0f, m1 = 1.0f;
        if (MODE == 2) {
            int b0 = gr0 / TT,       t0 = gr0 - b0 * TT;
            int b1 = (gr0 + 8) / TT, t1 = (gr0 + 8) - b1 * TT;
            m0 = (t0 < declen[b0]) ? 1.0f : 0.0f;
            m1 = (t1 < declen[b1]) ? 1.0f : 0.0f;
        }
        #pragma unroll
        for (int j = 0; j < 8; j++) {
            int gc = col0 + wn * 64 + j * 8 + ((lane & 3) << 1);
            if (gc + 1 < Ncols) {
                float bi0 = bias1[gc], bi1 = bias1[gc + 1];
                if (MODE == 0 && bias2) { bi0 += bias2[gc]; bi1 += bias2[gc + 1]; }
                float2 v0 = make_float2((acc[mi][j][0] + bi0) * m0, (acc[mi][j][1] + bi1) * m0);
                float2 v1 = make_float2((acc[mi][j][2] + bi0) * m1, (acc[mi][j][3] + bi1) * m1);
                *reinterpret_cast<float2*>(&C[(size_t)gr0 * ldc + gc]) = v0;
                *reinterpret_cast<float2*>(&C[(size_t)(gr0 + 8) * ldc + gc]) = v1;
            } else if (gc < Ncols) {
                float bi0 = bias1[gc];
                if (MODE == 0 && bias2) bi0 += bias2[gc];
                C[(size_t)gr0 * ldc + gc]       = (acc[mi][j][0] + bi0) * m0;
                C[(size_t)(gr0 + 8) * ldc + gc] = (acc[mi][j][2] + bi0) * m1;
            }
        }
    }
}

// ---------------- persistent LSTM recurrence (HMMA gates GEMM) ----------------
// 128 CTAs; CTA cid owns d-cols [4cid,4cid+4) -> 16 gate rows (n = 4q + r -> gate 512q + 4cid + r).
// W slice (bf16 hi/lo) resident in smem; h (bf16 hi/lo, ping-pong in global) staged per step via cp.async.
// Per-CTA step GEMM: M=128(b) x N=16(gates) x K=512, 3-pass split. Warp w owns rows [16w,16w+16).
#define R2_W_STRIDE 520
#define R2_SW_ELEMS (16 * R2_W_STRIDE)                  // bf16 per operand
#define R2_A_TILE   (128 * 40)                          // bf16 per operand per buffer
#define R2_A_OFF    (2 * R2_SW_ELEMS * 2)               // bytes: 33280
#define R2_SG_OFF   (R2_A_OFF + 2 * 2 * R2_A_TILE * 2)  // bytes: 74240
#define RSMEM_BYTES (R2_SG_OFF + 128 * 20 * 4)          // 84480

__global__ __launch_bounds__(256)
void k_recur(const __nv_bfloat16* __restrict__ Whi, const __nv_bfloat16* __restrict__ Wlo) {
    extern __shared__ __align__(16) char smrc[];
    __nv_bfloat16* sW = (__nv_bfloat16*)smrc;            // [2][16][520]
    float* sG = (float*)(smrc + R2_SG_OFF);              // [128][20]
    const uint32_t sbase = smem_u32(smrc);
    const uint32_t sWhiA = sbase;
    const uint32_t sWloA = sbase + R2_SW_ELEMS * 2;
    const uint32_t sAbase = sbase + R2_A_OFF;

    const int tid  = threadIdx.x;
    const int cid  = blockIdx.x;
    const int lane = tid & 31;
    const int w    = tid >> 5;
    const int mat  = lane >> 3, mr = lane & 7;
    const int rrowA = 16 * w + mr + ((mat & 1) << 3);
    const int nrowB = mr + ((mat >> 1) << 3);

    // load this CTA's 16 W rows (hi/lo) once
    for (int e = tid; e < 2048; e += 256) {
        int tsel = e >> 10, i = e & 1023;
        int n = i >> 6, v = i & 63;
        int gr = ((n >> 2) << 9) + cid * 4 + (n & 3);
        uint4 src = *reinterpret_cast<const uint4*>((tsel ? Wlo : Whi) + (size_t)gr * KK + v * 8);
        *reinterpret_cast<uint4*>(sW + tsel * R2_SW_ELEMS + n * R2_W_STRIDE + v * 8) = src;
    }
    __syncthreads();

    for (int t = 0; t < TT; t++) {
        const __nv_bfloat16* hinHi = g_hHi[t & 1];
        const __nv_bfloat16* hinLo = g_hLo[t & 1];
        __nv_bfloat16* houtHi = g_hHi[(t + 1) & 1];
        __nv_bfloat16* houtLo = g_hLo[(t + 1) & 1];

        auto stageA = [&](int ch, int buf) {
            #pragma unroll
            for (int e = tid; e < 1024; e += 256) {
                int tsel = e >> 9, i = e & 511;
                int r = i >> 2, q = i & 3;
                const __nv_bfloat16* src = (tsel ? hinLo : hinHi) + r * DD + ch * 32 + q * 8;
                cp_async16(sAbase + (uint32_t)((buf * 2 + tsel) * R2_A_TILE + r * 40 + q * 8) * 2, src, 16);
            }
            asm volatile("cp.async.commit_group;" ::: "memory");
        };

        float accA[4] = {0,0,0,0}, accB[4] = {0,0,0,0};  // n8 blocks 0 (gates 0-7) and 1 (8-15)

        stageA(0, 0);
        for (int ch = 0; ch < 16; ch++) {
            if (ch + 1 < 16) {
                stageA(ch + 1, (ch + 1) & 1);
                asm volatile("cp.async.wait_group 1;" ::: "memory");
            } else {
                asm volatile("cp.async.wait_group 0;" ::: "memory");
            }
            __syncthreads();
            const uint32_t aHi = sAbase + (uint32_t)((ch & 1) * 2 * R2_A_TILE) * 2;
            const uint32_t aLo = aHi + R2_A_TILE * 2;
            #pragma unroll
            for (int kk = 0; kk < 32; kk += 16) {
                const int acol = kk + ((mat >> 1) << 3);
                const int bcol = ch * 32 + kk + ((mat & 1) << 3);
                uint32_t ahi[4], alo[4], bhi[4], blo[4];
                ldsm_x4(ahi, aHi + (uint32_t)(rrowA * 40 + acol) * 2);
                ldsm_x4(bhi, sWhiA + (uint32_t)(nrowB * R2_W_STRIDE + bcol) * 2);
                mma_bf16(accA, ahi, &bhi[0]);
                mma_bf16(accB, ahi, &bhi[2]);
                ldsm_x4(blo, sWloA + (uint32_t)(nrowB * R2_W_STRIDE + bcol) * 2);
                mma_bf16(accA, ahi, &blo[0]);
                mma_bf16(accB, ahi, &blo[2]);
                ldsm_x4(alo, aLo + (uint32_t)(rrowA * 40 + acol) * 2);
                mma_bf16(accA, alo, &bhi[0]);
                mma_bf16(accB, alo, &bhi[2]);
            }
            __syncthreads();
        }

        // scatter acc to sG[b][n]
        {
            int r0 = 16 * w + (lane >> 2);
            int c0 = (lane & 3) * 2;
            *reinterpret_cast<float2*>(&sG[r0 * 20 + c0])           = make_float2(accA[0], accA[1]);
            *reinterpret_cast<float2*>(&sG[(r0 + 8) * 20 + c0])     = make_float2(accA[2], accA[3]);
            *reinterpret_cast<float2*>(&sG[r0 * 20 + 8 + c0])       = make_float2(accB[0], accB[1]);
            *reinterpret_cast<float2*>(&sG[(r0 + 8) * 20 + 8 + c0]) = make_float2(accB[2], accB[3]);
        }
        __syncthreads();

        // pointwise LSTM update
        #pragma unroll
        for (int e = tid; e < 512; e += 256) {
            int b = e >> 2, dl = e & 3;
            const float* xrow = g_X + (size_t)(b * TT + t) * G4 + cid * 4 + dl;
            float gi = sG[b * 20 + dl]      + xrow[0];
            float gf = sG[b * 20 + 4 + dl]  + xrow[512];
            float gg = sG[b * 20 + 8 + dl]  + xrow[1024];
            float go = sG[b * 20 + 12 + dl] + xrow[1536];
            float si = 1.0f / (1.0f + expf(-gi));
            float sf = 1.0f / (1.0f + expf(-gf));
            float tg = tanhf(gg);
            float so = 1.0f / (1.0f + expf(-go));
            int d = cid * 4 + dl;
            float cold = g_c[b * DD + d];
            float cnew = sf * cold + si * tg;
            float hnew = so * tanhf(cnew);
            __nv_bfloat16 hH = __float2bfloat16(hnew);
            __nv_bfloat16 hL = __float2bfloat16(hnew - __bfloat162float(hH));
            g_Ahi[(size_t)(b * TT + t) * KK + d] = hH;   // H history (split) for word GEMM
            g_Alo[(size_t)(b * TT + t) * KK + d] = hL;
            bool m = t < g_declen[b];
            unsigned short oH, oL;
            asm volatile("ld.global.cg.u16 %0, [%1];" : "=h"(oH) : "l"(hinHi + b * DD + d));
            asm volatile("ld.global.cg.u16 %0, [%1];" : "=h"(oL) : "l"(hinLo + b * DD + d));
            houtHi[b * DD + d] = m ? hH : __ushort_as_bfloat16(oH);
            houtLo[b * DD + d] = m ? hL : __ushort_as_bfloat16(oL);
            if (m) g_c[b * DD + d] = cnew;
        }
        // global barrier: release, then acquire-spin
        __threadfence();
        __syncthreads();
        if (tid == 0) {
            atomicAdd(&g_bar, 1u);
            unsigned target = (unsigned)(128 * (t + 1));
            unsigned v;
            do {
                asm volatile("ld.acquire.gpu.u32 %0, [%1];" : "=r"(v) : "l"(&g_bar));
            } while (v < target);
        }
        __syncthreads();
    }
}

// ---------------- launch ----------------
extern "C" void kernel_launch(void* const* d_in, const int* in_sizes, int n_in,
                              void* d_out, int out_size) {
    const float* img    = (const float*)d_in[0];
    const int*   caps   = (const int*)  d_in[1];
    const int*   caplen = (const int*)  d_in[2];
    const float* embtab = (const float*)d_in[3];
    const float* att1_w = (const float*)d_in[4];
    const float* att1_b = (const float*)d_in[5];
    const float* w_ih   = (const float*)d_in[6];
    const float* w_hh   = (const float*)d_in[7];
    const float* b_ih   = (const float*)d_in[8];
    const float* b_hh   = (const float*)d_in[9];
    const float* word_w = (const float*)d_in[10];
    const float* word_b = (const float*)d_in[11];
    float* out = (float*)d_out;

    float *pX, *pFeats, *pHbuf;
    __nv_bfloat16 *pAhi, *pAlo, *pBhi, *pBlo, *pHHi, *pHLo;
    int *pDeclen;
    cudaGetSymbolAddress((void**)&pX,     g_X);
    cudaGetSymbolAddress((void**)&pFeats, g_feats);
    cudaGetSymbolAddress((void**)&pHbuf,  g_hbuf);
    cudaGetSymbolAddress((void**)&pAhi,   g_Ahi);
    cudaGetSymbolAddress((void**)&pAlo,   g_Alo);
    cudaGetSymbolAddress((void**)&pBhi,   g_Bhi);
    cudaGetSymbolAddress((void**)&pBlo,   g_Blo);
    cudaGetSymbolAddress((void**)&pHHi,   g_hHi);
    cudaGetSymbolAddress((void**)&pHLo,   g_hLo);
    cudaGetSymbolAddress((void**)&pDeclen,g_declen);

    cudaFuncSetAttribute(k_recur, cudaFuncAttributeMaxDynamicSharedMemorySize, RSMEM_BYTES);
    cudaFuncSetAttribute(mma_gemm<0>, cudaFuncAttributeMaxDynamicSharedMemorySize, MG_SMEM);
    cudaFuncSetAttribute(mma_gemm<2>, cudaFuncAttributeMaxDynamicSharedMemorySize, MG_SMEM);

    // 0) sort / gather / tail outputs / zero c & barrier
    k_sort<<<1, BB>>>(caplen, caps, out, (long long)out_size);
    // 1) split w_ih -> B buffers
    k_split<<<(G4 * KK / 4 + 255) / 256, 256>>>((const float4*)w_ih, (uint2*)pBhi, (uint2*)pBlo, G4 * KK / 4);
    // 2) gather+split emb -> A buffers
    k_split_emb<<<MROWS, 128>>>(embtab);
    // 3) X = emb @ w_ih^T + b_ih + b_hh  (HMMA)  <- ncu profiled slot
    {
        dim3 grid(G4 / 128, MROWS / 128);
        mma_gemm<0><<<grid, 256, MG_SMEM>>>(pAhi, pAlo, pBhi, pBlo, b_ih, b_hh, pX, G4, G4, nullptr);
    }
    // 4) mean features (sorted)
    k_mean<<<BB, 256>>>(img);
    // 5) h0 = feats @ att1_w^T + att1_b (fp32)
    {
        dim3 grid(DD / 64, BB / 64);
        gemm_nt<64, 64, 16, 4, 4><<<grid, 256>>>(
            pFeats, FEATN, att1_w, FEATN, att1_b, pHbuf, DD, FEATN);
    }
    // 6) split h0 -> hHi[0]/hLo[0]
    k_split<<<(BB * DD / 4 + 255) / 256, 256>>>((const float4*)pHbuf, (uint2*)pHHi, (uint2*)pHLo, BB * DD / 4);
    // 7) split w_hh -> B buffers (w_ih split already consumed by step 3)
    k_split<<<(G4 * KK / 4 + 255) / 256, 256>>>((const float4*)w_hh, (uint2*)pBhi, (uint2*)pBlo, G4 * KK / 4);
    // 8) persistent recurrence (HMMA); writes H split directly into A buffers
    k_recur<<<128, 256, RSMEM_BYTES>>>(pBhi, pBlo);
    // 9) split word_w -> B buffers
    k_split<<<(VV * KK / 4 + 255) / 256, 256>>>((const float4*)word_w, (uint2*)pBhi, (uint2*)pBlo, VV * KK / 4);
    // 10) predictions = mask * (H @ word_w^T + word_b)  (HMMA)
    {
        dim3 grid((VV + 127) / 128, MROWS / 128);
        mma_gemm<2><<<grid, 256, MG_SMEM>>>(pAhi, pAlo, pBhi, pBlo, word_b, nullptr, out, VV, VV, pDeclen);
    }
}

// round 15
// speedup vs baseline: 2.8348x; 1.1019x over previous
#include <cuda_runtime.h>
#include <cuda_bf16.h>
#include <cstdint>
#include <math.h>

// Problem constants
#define BB   128
#define LLEN 52
#define TT   51
#define EE   512
#define DD   512
#define VV   10000
#define FEATN 2048
#define NPP  196
#define G4   2048
#define KK   512
#define MROWS (BB*TT)        // 6528

// ---------------- scratch ----------------
__device__ float g_X[(size_t)MROWS * G4];
__device__ float g_feats[(size_t)BB * FEATN];
__device__ float g_hbuf[BB * DD];            // h0 fp32 staging
__device__ float g_c[BB * DD];
__device__ int   g_sort[BB];
__device__ int   g_declen[BB];
__device__ int   g_capsS[BB * LLEN];
__device__ int   g_rowmap[MROWS];
__device__ unsigned g_bar;
// h state in bf16 hi/lo split, ping-pong
__device__ __nv_bfloat16 g_hHi[2][BB * DD];
__device__ __nv_bfloat16 g_hLo[2][BB * DD];
// bf16 split buffers (A: emb-gather then H-history; B: w_ih, then w_hh, then word_w)
__device__ __nv_bfloat16 g_Ahi[(size_t)MROWS * KK];
__device__ __nv_bfloat16 g_Alo[(size_t)MROWS * KK];
__device__ __nv_bfloat16 g_Bhi[(size_t)VV * KK];
__device__ __nv_bfloat16 g_Blo[(size_t)VV * KK];

// ---------------- small helpers ----------------
__device__ __forceinline__ uint32_t smem_u32(const void* p) {
    return (uint32_t)__cvta_generic_to_shared(p);
}
__device__ __forceinline__ void ldsm_x4(uint32_t* r, uint32_t addr) {
    asm volatile("ldmatrix.sync.aligned.m8n8.x4.shared.b16 {%0,%1,%2,%3}, [%4];"
                 : "=r"(r[0]), "=r"(r[1]), "=r"(r[2]), "=r"(r[3]) : "r"(addr));
}
__device__ __forceinline__ void mma_bf16(float* c, const uint32_t* a, const uint32_t* b) {
    asm volatile("mma.sync.aligned.m16n8k16.row.col.f32.bf16.bf16.f32 "
                 "{%0,%1,%2,%3},{%4,%5,%6,%7},{%8,%9},{%0,%1,%2,%3};"
                 : "+f"(c[0]), "+f"(c[1]), "+f"(c[2]), "+f"(c[3])
                 : "r"(a[0]), "r"(a[1]), "r"(a[2]), "r"(a[3]), "r"(b[0]), "r"(b[1]));
}
__device__ __forceinline__ void cp_async16(uint32_t dst, const void* src, int src_bytes) {
    asm volatile("cp.async.cg.shared.global [%0], [%1], 16, %2;"
                 :: "r"(dst), "l"(src), "r"(src_bytes) : "memory");
}

// ---------------- sort / gather ----------------
__global__ void k_sort(const int* __restrict__ caplen, const int* __restrict__ caps,
                       float* __restrict__ out, long long out_size) {
    __shared__ int lens[BB];
    int b = threadIdx.x;
    lens[b] = caplen[b];
    if (b == 0) g_bar = 0u;
    __syncthreads();
    int my = lens[b];
    int rank = 0;
    for (int j = 0; j < BB; j++) {
        int lj = lens[j];
        if (lj > my || (lj == my && j < b)) rank++;
    }
    g_sort[rank] = b;
    __syncthreads();
    int s = g_sort[b];
    int dl = lens[s] - 1;
    g_declen[b] = dl;
    for (int l = 0; l < LLEN; l++) g_capsS[b * LLEN + l] = caps[s * LLEN + l];
    for (int t = 0; t < TT; t++)   g_rowmap[b * TT + t] = g_capsS[b * LLEN + t];
    for (int d = 0; d < DD; d++)   g_c[b * DD + d] = 0.0f;
    long long off = (long long)MROWS * VV;
    if (out_size >= off + (long long)BB * LLEN + 2 * BB) {
        for (int l = 0; l < LLEN; l++) out[off + b * LLEN + l] = (float)g_capsS[b * LLEN + l];
        out[off + (long long)BB * LLEN + b]      = (float)dl;
        out[off + (long long)BB * LLEN + BB + b] = (float)s;
    }
}

// ---------------- mean features ----------------
__global__ __launch_bounds__(256) void k_mean(const float* __restrict__ img) {
    int p = blockIdx.x;
    int s = g_sort[p];
    const float* base = img + (long long)s * NPP * FEATN;
    int f0 = threadIdx.x;
    float acc[8] = {0,0,0,0,0,0,0,0};
    for (int q = 0; q < NPP; q++) {
        const float* rowp = base + (long long)q * FEATN;
        #pragma unroll
        for (int u = 0; u < 8; u++) acc[u] += rowp[f0 + u * 256];
    }
    #pragma unroll
    for (int u = 0; u < 8; u++)
        g_feats[(long long)p * FEATN + f0 + u * 256] = acc[u] * (1.0f / 196.0f);
}

// ---------------- SIMT GEMM (small h0 only) ----------------
template<int BM, int BN, int BK, int TM, int TN>
__global__ __launch_bounds__((BM/TM)*(BN/TN)) void gemm_nt(
    const float* __restrict__ A, int lda,
    const float* __restrict__ B, int ldb,
    const float* __restrict__ bias1,
    float* __restrict__ C, int ldc, int K)
{
    constexpr int NT = (BM / TM) * (BN / TN);
    __shared__ float As[BK][BM + 4];
    __shared__ float Bs[BK][BN + 4];
    const int tid = threadIdx.x;
    const int tx = tid % (BN / TN);
    const int ty = tid / (BN / TN);
    const int row0 = blockIdx.y * BM;
    const int col0 = blockIdx.x * BN;

    float acc[TM][TN];
    #pragma unroll
    for (int i = 0; i < TM; i++)
        #pragma unroll
        for (int j = 0; j < TN; j++) acc[i][j] = 0.0f;

    for (int k0 = 0; k0 < K; k0 += BK) {
        for (int e = tid; e < BM * BK; e += NT) {
            int r = e / BK, k = e % BK;
            As[k][r] = A[(long long)(row0 + r) * lda + k0 + k];
        }
        for (int e = tid; e < BN * BK; e += NT) {
            int c = e / BK, k = e % BK;
            Bs[k][c] = B[(long long)(col0 + c) * ldb + k0 + k];
        }
        __syncthreads();
        #pragma unroll
        for (int kk = 0; kk < BK; kk++) {
            float ra[TM], rb[TN];
            #pragma unroll
            for (int i = 0; i < TM; i += 4) {
                float4 v = *reinterpret_cast<const float4*>(&As[kk][ty * TM + i]);
                ra[i] = v.x; ra[i+1] = v.y; ra[i+2] = v.z; ra[i+3] = v.w;
            }
            #pragma unroll
            for (int j = 0; j < TN; j += 4) {
                float4 v = *reinterpret_cast<const float4*>(&Bs[kk][tx * TN + j]);
                rb[j] = v.x; rb[j+1] = v.y; rb[j+2] = v.z; rb[j+3] = v.w;
            }
            #pragma unroll
            for (int i = 0; i < TM; i++)
                #pragma unroll
                for (int j = 0; j < TN; j++)
                    acc[i][j] += ra[i] * rb[j];
        }
        __syncthreads();
    }
    #pragma unroll
    for (int i = 0; i < TM; i++) {
        int gr = row0 + ty * TM + i;
        #pragma unroll
        for (int j = 0; j < TN; j++) {
            int gc = col0 + tx * TN + j;
            C[(long long)gr * ldc + gc] = acc[i][j] + bias1[gc];
        }
    }
}

// ---------------- bf16 split helpers ----------------
__device__ __forceinline__ void split2(float a, float b, uint32_t& h, uint32_t& l) {
    __nv_bfloat16 ha = __float2bfloat16(a);
    __nv_bfloat16 hb = __float2bfloat16(b);
    float ra = a - __bfloat162float(ha);
    float rb = b - __bfloat162float(hb);
    __nv_bfloat16 la = __float2bfloat16(ra);
    __nv_bfloat16 lb = __float2bfloat16(rb);
    h = ((uint32_t)__bfloat16_as_ushort(hb) << 16) | (uint32_t)__bfloat16_as_ushort(ha);
    l = ((uint32_t)__bfloat16_as_ushort(lb) << 16) | (uint32_t)__bfloat16_as_ushort(la);
}

__global__ __launch_bounds__(256) void k_split(const float4* __restrict__ src,
                                               uint2* __restrict__ hi, uint2* __restrict__ lo, int n4) {
    int i = blockIdx.x * 256 + threadIdx.x;
    if (i >= n4) return;
    float4 v = src[i];
    uint2 h, l;
    split2(v.x, v.y, h.x, l.x);
    split2(v.z, v.w, h.y, l.y);
    hi[i] = h;
    lo[i] = l;
}

__global__ __launch_bounds__(128) void k_split_emb(const float* __restrict__ emb) {
    int m = blockIdx.x;
    int tok = g_rowmap[m];
    float4 v = reinterpret_cast<const float4*>(emb + (long long)tok * EE)[threadIdx.x];
    uint2 h, l;
    split2(v.x, v.y, h.x, l.x);
    split2(v.z, v.w, h.y, l.y);
    reinterpret_cast<uint2*>(g_Ahi + (long long)m * KK)[threadIdx.x] = h;
    reinterpret_cast<uint2*>(g_Alo + (long long)m * KK)[threadIdx.x] = l;
}

// ---------------- mma.sync bf16 3-pass split GEMM (cp.async double-buffered) ----------------
#define MG_TILE_ELEMS (128 * 40)
#define MG_STAGE_BYTES (4 * MG_TILE_ELEMS * 2)
#define MG_SMEM (2 * MG_STAGE_BYTES)

template<int MODE>
__global__ __launch_bounds__(256, 2)
void mma_gemm(const __nv_bfloat16* __restrict__ Ahi, const __nv_bfloat16* __restrict__ Alo,
              const __nv_bfloat16* __restrict__ Bhi, const __nv_bfloat16* __restrict__ Blo,
              const float* __restrict__ bias1, const float* __restrict__ bias2,
              float* __restrict__ C, int ldc, int Ncols,
              const int* __restrict__ declen)
{
    extern __shared__ __align__(16) __nv_bfloat16 smp[];
    const int tid  = threadIdx.x;
    const int lane = tid & 31;
    const int w    = tid >> 5;
    const int wm   = w >> 1;
    const int wn   = w & 1;
    const int row0 = blockIdx.y * 128;
    const int col0 = blockIdx.x * 128;
    const int mat  = lane >> 3;
    const int mr   = lane & 7;

    float acc[2][8][4];
    #pragma unroll
    for (int i = 0; i < 2; i++)
        #pragma unroll
        for (int j = 0; j < 8; j++)
            #pragma unroll
            for (int q = 0; q < 4; q++) acc[i][j][q] = 0.0f;

    auto stage_load = [&](int ch, int buf) {
        const int k0 = ch * 32;
        __nv_bfloat16* base = smp + (size_t)buf * 4 * MG_TILE_ELEMS;
        #pragma unroll
        for (int e = tid; e < 2048; e += 256) {
            int tsel = e >> 9;
            int i = e & 511;
            int r = i >> 2, q = i & 3;
            const __nv_bfloat16* src;
            int sz = 16;
            if (tsel < 2) {
                src = (tsel == 0 ? Ahi : Alo) + (size_t)(row0 + r) * KK + k0 + q * 8;
            } else {
                int gc = col0 + r;
                int gcs = (gc < Ncols) ? gc : 0;
                src = (tsel == 2 ? Bhi : Blo) + (size_t)gcs * KK + k0 + q * 8;
                sz = (gc < Ncols) ? 16 : 0;
            }
            cp_async16(smem_u32(base + tsel * MG_TILE_ELEMS + r * 40 + q * 8), src, sz);
        }
        asm volatile("cp.async.commit_group;" ::: "memory");
    };

    stage_load(0, 0);

    for (int ch = 0; ch < 16; ch++) {
        if (ch + 1 < 16) {
            stage_load(ch + 1, (ch + 1) & 1);
            asm volatile("cp.async.wait_group 1;" ::: "memory");
        } else {
            asm volatile("cp.async.wait_group 0;" ::: "memory");
        }
        __syncthreads();

        const uint32_t sbase = smem_u32(smp) + (uint32_t)((ch & 1) * MG_STAGE_BYTES);
        const uint32_t sA0 = sbase;
        const uint32_t sA1 = sbase + MG_TILE_ELEMS * 2;
        const uint32_t sB0 = sbase + MG_TILE_ELEMS * 4;
        const uint32_t sB1 = sbase + MG_TILE_ELEMS * 6;

        #pragma unroll
        for (int kk = 0; kk < 32; kk += 16) {
            uint32_t ahi[2][4], alo[2][4], bhi[8][2], blo[8][2];
            const int acol = kk + ((mat >> 1) << 3);
            const int bcolA = kk + ((mat & 1) << 3);
            #pragma unroll
            for (int mi = 0; mi < 2; mi++) {
                int rrow = wm * 32 + mi * 16 + mr + ((mat & 1) << 3);
                ldsm_x4(ahi[mi], sA0 + (uint32_t)(rrow * 40 + acol) * 2);
            }
            #pragma unroll
            for (int j2 = 0; j2 < 4; j2++) {
                int nrow = wn * 64 + j2 * 16 + mr + ((mat >> 1) << 3);
                uint32_t r4[4];
                ldsm_x4(r4, sB0 + (uint32_t)(nrow * 40 + bcolA) * 2);
                bhi[2*j2][0] = r4[0]; bhi[2*j2][1] = r4[1];
                bhi[2*j2+1][0] = r4[2]; bhi[2*j2+1][1] = r4[3];
            }
            #pragma unroll
            for (int mi = 0; mi < 2; mi++)
                #pragma unroll
                for (int j = 0; j < 8; j++)
                    mma_bf16(acc[mi][j], ahi[mi], bhi[j]);
            #pragma unroll
            for (int j2 = 0; j2 < 4; j2++) {
                int nrow = wn * 64 + j2 * 16 + mr + ((mat >> 1) << 3);
                uint32_t r4[4];
                ldsm_x4(r4, sB1 + (uint32_t)(nrow * 40 + bcolA) * 2);
                blo[2*j2][0] = r4[0]; blo[2*j2][1] = r4[1];
                blo[2*j2+1][0] = r4[2]; blo[2*j2+1][1] = r4[3];
            }
            #pragma unroll
            for (int mi = 0; mi < 2; mi++)
                #pragma unroll
                for (int j = 0; j < 8; j++)
                    mma_bf16(acc[mi][j], ahi[mi], blo[j]);
            #pragma unroll
            for (int mi = 0; mi < 2; mi++) {
                int rrow = wm * 32 + mi * 16 + mr + ((mat & 1) << 3);
                ldsm_x4(alo[mi], sA1 + (uint32_t)(rrow * 40 + acol) * 2);
            }
            #pragma unroll
            for (int mi = 0; mi < 2; mi++)
                #pragma unroll
                for (int j = 0; j < 8; j++)
                    mma_bf16(acc[mi][j], alo[mi], bhi[j]);
        }
        __syncthreads();
    }

    #pragma unroll
    for (int mi = 0; mi < 2; mi++) {
        int gr0 = row0 + wm * 32 + mi * 16 + (lane >> 2);
        float m0 = 1.0f, m1 = 1.0f;
        if (MODE == 2) {
            int b0 = gr0 / TT,       t0 = gr0 - b0 * TT;
            int b1 = (gr0 + 8) / TT, t1 = (gr0 + 8) - b1 * TT;
            m0 = (t0 < declen[b0]) ? 1.0f : 0.0f;
            m1 = (t1 < declen[b1]) ? 1.0f : 0.0f;
        }
        #pragma unroll
        for (int j = 0; j < 8; j++) {
            int gc = col0 + wn * 64 + j * 8 + ((lane & 3) << 1);
            if (gc + 1 < Ncols) {
                float bi0 = bias1[gc], bi1 = bias1[gc + 1];
                if (MODE == 0 && bias2) { bi0 += bias2[gc]; bi1 += bias2[gc + 1]; }
                float2 v0 = make_float2((acc[mi][j][0] + bi0) * m0, (acc[mi][j][1] + bi1) * m0);
                float2 v1 = make_float2((acc[mi][j][2] + bi0) * m1, (acc[mi][j][3] + bi1) * m1);
                *reinterpret_cast<float2*>(&C[(size_t)gr0 * ldc + gc]) = v0;
                *reinterpret_cast<float2*>(&C[(size_t)(gr0 + 8) * ldc + gc]) = v1;
            } else if (gc < Ncols) {
                float bi0 = bias1[gc];
                if (MODE == 0 && bias2) bi0 += bias2[gc];
                C[(size_t)gr0 * ldc + gc]       = (acc[mi][j][0] + bi0) * m0;
                C[(size_t)(gr0 + 8) * ldc + gc] = (acc[mi][j][2] + bi0) * m1;
            }
        }
    }
}

// ---------------- persistent LSTM recurrence (HMMA gates GEMM, BK=128) ----------------
// 128 CTAs; CTA cid owns d-cols [4cid,4cid+4) -> 16 gate rows.
// W slice (bf16 hi/lo) resident in smem; h staged per step via cp.async in 4 chunks of K=128.
#define R2_W_STRIDE 520
#define R2_SW_ELEMS (16 * R2_W_STRIDE)                  // bf16 per operand
#define R2_A_STRIDE 136
#define R2_A_TILE   (128 * R2_A_STRIDE)                 // 17408 bf16 per op per buffer
#define R2_A_OFF    (2 * R2_SW_ELEMS * 2)               // bytes: 33280
#define R2_SG_OFF   (R2_A_OFF + 2 * 2 * R2_A_TILE * 2)  // bytes: 172544
#define RSMEM_BYTES (R2_SG_OFF + 128 * 20 * 4)          // 182784

__global__ __launch_bounds__(256)
void k_recur(const __nv_bfloat16* __restrict__ Whi, const __nv_bfloat16* __restrict__ Wlo) {
    extern __shared__ __align__(16) char smrc[];
    __nv_bfloat16* sW = (__nv_bfloat16*)smrc;            // [2][16][520]
    float* sG = (float*)(smrc + R2_SG_OFF);              // [128][20]
    const uint32_t sbase = smem_u32(smrc);
    const uint32_t sWhiA = sbase;
    const uint32_t sWloA = sbase + R2_SW_ELEMS * 2;
    const uint32_t sAbase = sbase + R2_A_OFF;

    const int tid  = threadIdx.x;
    const int cid  = blockIdx.x;
    const int lane = tid & 31;
    const int w    = tid >> 5;
    const int mat  = lane >> 3, mr = lane & 7;
    const int rrowA = 16 * w + mr + ((mat & 1) << 3);
    const int nrowB = mr + ((mat >> 1) << 3);

    // load this CTA's 16 W rows (hi/lo) once
    for (int e = tid; e < 2048; e += 256) {
        int tsel = e >> 10, i = e & 1023;
        int n = i >> 6, v = i & 63;
        int gr = ((n >> 2) << 9) + cid * 4 + (n & 3);
        uint4 src = *reinterpret_cast<const uint4*>((tsel ? Wlo : Whi) + (size_t)gr * KK + v * 8);
        *reinterpret_cast<uint4*>(sW + tsel * R2_SW_ELEMS + n * R2_W_STRIDE + v * 8) = src;
    }
    __syncthreads();

    for (int t = 0; t < TT; t++) {
        const __nv_bfloat16* hinHi = g_hHi[t & 1];
        const __nv_bfloat16* hinLo = g_hLo[t & 1];
        __nv_bfloat16* houtHi = g_hHi[(t + 1) & 1];
        __nv_bfloat16* houtLo = g_hLo[(t + 1) & 1];

        auto stageA = [&](int ch, int buf) {
            #pragma unroll
            for (int e = tid; e < 4096; e += 256) {
                int tsel = e >> 11, i = e & 2047;
                int r = i >> 4, q = i & 15;
                const __nv_bfloat16* src = (tsel ? hinLo : hinHi) + r * DD + ch * 128 + q * 8;
                cp_async16(sAbase + (uint32_t)((buf * 2 + tsel) * R2_A_TILE + r * R2_A_STRIDE + q * 8) * 2, src, 16);
            }
            asm volatile("cp.async.commit_group;" ::: "memory");
        };

        float accA[4] = {0,0,0,0}, accB[4] = {0,0,0,0};  // n8 blocks 0 (gates 0-7) and 1 (8-15)

        stageA(0, 0);
        for (int ch = 0; ch < 4; ch++) {
            if (ch + 1 < 4) {
                stageA(ch + 1, (ch + 1) & 1);
                asm volatile("cp.async.wait_group 1;" ::: "memory");
            } else {
                asm volatile("cp.async.wait_group 0;" ::: "memory");
            }
            __syncthreads();
            const uint32_t aHi = sAbase + (uint32_t)((ch & 1) * 2 * R2_A_TILE) * 2;
            const uint32_t aLo = aHi + R2_A_TILE * 2;
            #pragma unroll
            for (int kk = 0; kk < 128; kk += 16) {
                const int acol = kk + ((mat >> 1) << 3);
                const int bcol = ch * 128 + kk + ((mat & 1) << 3);
                uint32_t ahi[4], alo[4], bhi[4], blo[4];
                ldsm_x4(ahi, aHi + (uint32_t)(rrowA * R2_A_STRIDE + acol) * 2);
                ldsm_x4(bhi, sWhiA + (uint32_t)(nrowB * R2_W_STRIDE + bcol) * 2);
                mma_bf16(accA, ahi, &bhi[0]);
                mma_bf16(accB, ahi, &bhi[2]);
                ldsm_x4(blo, sWloA + (uint32_t)(nrowB * R2_W_STRIDE + bcol) * 2);
                mma_bf16(accA, ahi, &blo[0]);
                mma_bf16(accB, ahi, &blo[2]);
                ldsm_x4(alo, aLo + (uint32_t)(rrowA * R2_A_STRIDE + acol) * 2);
                mma_bf16(accA, alo, &bhi[0]);
                mma_bf16(accB, alo, &bhi[2]);
            }
            __syncthreads();
        }

        // scatter acc to sG[b][n]
        {
            int r0 = 16 * w + (lane >> 2);
            int c0 = (lane & 3) * 2;
            *reinterpret_cast<float2*>(&sG[r0 * 20 + c0])           = make_float2(accA[0], accA[1]);
            *reinterpret_cast<float2*>(&sG[(r0 + 8) * 20 + c0])     = make_float2(accA[2], accA[3]);
            *reinterpret_cast<float2*>(&sG[r0 * 20 + 8 + c0])       = make_float2(accB[0], accB[1]);
            *reinterpret_cast<float2*>(&sG[(r0 + 8) * 20 + 8 + c0]) = make_float2(accB[2], accB[3]);
        }
        __syncthreads();

        // pointwise LSTM update
        #pragma unroll
        for (int e = tid; e < 512; e += 256) {
            int b = e >> 2, dl = e & 3;
            const float* xrow = g_X + (size_t)(b * TT + t) * G4 + cid * 4 + dl;
            float gi = sG[b * 20 + dl]      + xrow[0];
            float gf = sG[b * 20 + 4 + dl]  + xrow[512];
            float gg = sG[b * 20 + 8 + dl]  + xrow[1024];
            float go = sG[b * 20 + 12 + dl] + xrow[1536];
            float si = 1.0f / (1.0f + expf(-gi));
            float sf = 1.0f / (1.0f + expf(-gf));
            float tg = tanhf(gg);
            float so = 1.0f / (1.0f + expf(-go));
            int d = cid * 4 + dl;
            float cold = g_c[b * DD + d];
            float cnew = sf * cold + si * tg;
            float hnew = so * tanhf(cnew);
            __nv_bfloat16 hH = __float2bfloat16(hnew);
            __nv_bfloat16 hL = __float2bfloat16(hnew - __bfloat162float(hH));
            g_Ahi[(size_t)(b * TT + t) * KK + d] = hH;   // H history (split) for word GEMM
            g_Alo[(size_t)(b * TT + t) * KK + d] = hL;
            bool m = t < g_declen[b];
            unsigned short oH, oL;
            asm volatile("ld.global.cg.u16 %0, [%1];" : "=h"(oH) : "l"(hinHi + b * DD + d));
            asm volatile("ld.global.cg.u16 %0, [%1];" : "=h"(oL) : "l"(hinLo + b * DD + d));
            houtHi[b * DD + d] = m ? hH : __ushort_as_bfloat16(oH);
            houtLo[b * DD + d] = m ? hL : __ushort_as_bfloat16(oL);
            if (m) g_c[b * DD + d] = cnew;
        }
        // global barrier: release, then acquire-spin
        __threadfence();
        __syncthreads();
        if (tid == 0) {
            atomicAdd(&g_bar, 1u);
            unsigned target = (unsigned)(128 * (t + 1));
            unsigned v;
            do {
                asm volatile("ld.acquire.gpu.u32 %0, [%1];" : "=r"(v) : "l"(&g_bar));
            } while (v < target);
        }
        __syncthreads();
    }
}

// ---------------- launch ----------------
extern "C" void kernel_launch(void* const* d_in, const int* in_sizes, int n_in,
                              void* d_out, int out_size) {
    const float* img    = (const float*)d_in[0];
    const int*   caps   = (const int*)  d_in[1];
    const int*   caplen = (const int*)  d_in[2];
    const float* embtab = (const float*)d_in[3];
    const float* att1_w = (const float*)d_in[4];
    const float* att1_b = (const float*)d_in[5];
    const float* w_ih   = (const float*)d_in[6];
    const float* w_hh   = (const float*)d_in[7];
    const float* b_ih   = (const float*)d_in[8];
    const float* b_hh   = (const float*)d_in[9];
    const float* word_w = (const float*)d_in[10];
    const float* word_b = (const float*)d_in[11];
    float* out = (float*)d_out;

    float *pX, *pFeats, *pHbuf;
    __nv_bfloat16 *pAhi, *pAlo, *pBhi, *pBlo, *pHHi, *pHLo;
    int *pDeclen;
    cudaGetSymbolAddress((void**)&pX,     g_X);
    cudaGetSymbolAddress((void**)&pFeats, g_feats);
    cudaGetSymbolAddress((void**)&pHbuf,  g_hbuf);
    cudaGetSymbolAddress((void**)&pAhi,   g_Ahi);
    cudaGetSymbolAddress((void**)&pAlo,   g_Alo);
    cudaGetSymbolAddress((void**)&pBhi,   g_Bhi);
    cudaGetSymbolAddress((void**)&pBlo,   g_Blo);
    cudaGetSymbolAddress((void**)&pHHi,   g_hHi);
    cudaGetSymbolAddress((void**)&pHLo,   g_hLo);
    cudaGetSymbolAddress((void**)&pDeclen,g_declen);

    cudaFuncSetAttribute(k_recur, cudaFuncAttributeMaxDynamicSharedMemorySize, RSMEM_BYTES);
    cudaFuncSetAttribute(mma_gemm<0>, cudaFuncAttributeMaxDynamicSharedMemorySize, MG_SMEM);
    cudaFuncSetAttribute(mma_gemm<2>, cudaFuncAttributeMaxDynamicSharedMemorySize, MG_SMEM);

    // 0) sort / gather / tail outputs / zero c & barrier
    k_sort<<<1, BB>>>(caplen, caps, out, (long long)out_size);
    // 1) split w_ih -> B buffers
    k_split<<<(G4 * KK / 4 + 255) / 256, 256>>>((const float4*)w_ih, (uint2*)pBhi, (uint2*)pBlo, G4 * KK / 4);
    // 2) gather+split emb -> A buffers
    k_split_emb<<<MROWS, 128>>>(embtab);
    // 3) X = emb @ w_ih^T + b_ih + b_hh  (HMMA)  <- ncu profiled slot
    {
        dim3 grid(G4 / 128, MROWS / 128);
        mma_gemm<0><<<grid, 256, MG_SMEM>>>(pAhi, pAlo, pBhi, pBlo, b_ih, b_hh, pX, G4, G4, nullptr);
    }
    // 4) mean features (sorted)
    k_mean<<<BB, 256>>>(img);
    // 5) h0 = feats @ att1_w^T + att1_b (fp32)
    {
        dim3 grid(DD / 64, BB / 64);
        gemm_nt<64, 64, 16, 4, 4><<<grid, 256>>>(
            pFeats, FEATN, att1_w, FEATN, att1_b, pHbuf, DD, FEATN);
    }
    // 6) split h0 -> hHi[0]/hLo[0]
    k_split<<<(BB * DD / 4 + 255) / 256, 256>>>((const float4*)pHbuf, (uint2*)pHHi, (uint2*)pHLo, BB * DD / 4);
    // 7) split w_hh -> B buffers
    k_split<<<(G4 * KK / 4 + 255) / 256, 256>>>((const float4*)w_hh, (uint2*)pBhi, (uint2*)pBlo, G4 * KK / 4);
    // 8) persistent recurrence (HMMA, BK=128); writes H split directly into A buffers
    k_recur<<<128, 256, RSMEM_BYTES>>>(pBhi, pBlo);
    // 9) split word_w -> B buffers
    k_split<<<(VV * KK / 4 + 255) / 256, 256>>>((const float4*)word_w, (uint2*)pBhi, (uint2*)pBlo, VV * KK / 4);
    // 10) predictions = mask * (H @ word_w^T + word_b)  (HMMA)
    {
        dim3 grid((VV + 127) / 128, MROWS / 128);
        mma_gemm<2><<<grid, 256, MG_SMEM>>>(pAhi, pAlo, pBhi, pBlo, word_b, nullptr, out, VV, VV, pDeclen);
    }
}